// round 1
// baseline (speedup 1.0000x reference)
#include <cuda_runtime.h>
#include <math.h>

#define T_TOK 2048
#define DIM   512
#define MOE   256
#define NE    64
#define NG    8
#define TOPKG 4
#define KSEL  8
#define RSCALE 2.5f
#define CAP   1024
#define ROWT  32

__device__ int   g_count[NE];
__device__ int   g_rows[NE][CAP];
__device__ float g_wt[NE][CAP];

// ---------------------------------------------------------------------------
// Kernel 0: zero output + expert counters
// ---------------------------------------------------------------------------
__global__ void zero_kernel(float* __restrict__ out) {
    int i = blockIdx.x * blockDim.x + threadIdx.x;
    if (i < T_TOK * DIM) out[i] = 0.0f;
    if (i < NE) g_count[i] = 0;
}

// ---------------------------------------------------------------------------
// Kernel 1: gating. 1 block per token, 64 threads (one per expert).
// ---------------------------------------------------------------------------
__global__ __launch_bounds__(64) void gate_kernel(
    const float* __restrict__ x,
    const float* __restrict__ gate_w,
    const float* __restrict__ gate_b)
{
    __shared__ float xs[DIM];
    __shared__ float gws[64][68];   // padded: 4-way max conflict on LDS.128
    __shared__ float scores[NE];
    __shared__ float sb[NE];        // biased scores; reused as candidate array

    const int t   = blockIdx.x;
    const int tid = threadIdx.x;

    // load token row
    const float4* x4 = (const float4*)(x + (size_t)t * DIM);
    ((float4*)xs)[tid]      = x4[tid];
    ((float4*)xs)[64 + tid] = x4[64 + tid];
    __syncthreads();

    float acc = 0.0f;
    const float4* gw4 = (const float4*)gate_w;
    for (int kc = 0; kc < DIM; kc += 64) {
        __syncthreads();
        // stage gate_w[:, kc:kc+64] -> gws[e][kk]
        #pragma unroll
        for (int j = 0; j < 16; j++) {
            int idx = j * 64 + tid;          // 1024 float4
            int e   = idx >> 4;
            int m4  = idx & 15;
            *(float4*)&gws[e][m4 * 4] = gw4[(size_t)e * (DIM/4) + (kc >> 2) + m4];
        }
        __syncthreads();
        #pragma unroll
        for (int kk = 0; kk < 64; kk += 4) {
            float4 wv = *(float4*)&gws[tid][kk];
            float4 xv = *(float4*)&xs[kc + kk];
            acc += xv.x * wv.x + xv.y * wv.y + xv.z * wv.z + xv.w * wv.w;
        }
    }
    float sc = 1.0f / (1.0f + expf(-acc));
    scores[tid] = sc;
    sb[tid]     = sc + gate_b[tid];
    __syncthreads();

    if (tid == 0) {
        const float NEG = -3.0e38f;
        // group scores = sum of top-2 per group (over biased scores)
        float gsc[NG];
        #pragma unroll
        for (int g = 0; g < NG; g++) {
            float m1 = NEG, m2 = NEG;
            #pragma unroll
            for (int j = 0; j < 8; j++) {
                float v = sb[g * 8 + j];
                if (v > m1) { m2 = m1; m1 = v; }
                else if (v > m2) { m2 = v; }
            }
            gsc[g] = m1 + m2;
        }
        // top-4 groups (ties -> lowest index, via strict >)
        bool gsel[NG];
        #pragma unroll
        for (int g = 0; g < NG; g++) gsel[g] = false;
        for (int it = 0; it < TOPKG; it++) {
            int bg = -1; float bv = NEG;
            #pragma unroll
            for (int g = 0; g < NG; g++)
                if (!gsel[g] && gsc[g] > bv) { bv = gsc[g]; bg = g; }
            gsel[bg] = true;
        }
        // mask non-selected groups in-place
        for (int e = 0; e < NE; e++)
            if (!gsel[e >> 3]) sb[e] = NEG;
        // top-8 experts
        int   idxs[KSEL];
        float wts[KSEL];
        float wsum = 0.0f;
        for (int k = 0; k < KSEL; k++) {
            int bi = 0; float bv = NEG;
            for (int e = 0; e < NE; e++)
                if (sb[e] > bv) { bv = sb[e]; bi = e; }
            sb[bi] = NEG;
            idxs[k] = bi;
            wts[k]  = scores[bi];     // pre-bias sigmoid score
            wsum   += wts[k];
        }
        float inv = RSCALE / wsum;
        for (int k = 0; k < KSEL; k++) {
            int e = idxs[k];
            int pos = atomicAdd(&g_count[e], 1);
            if (pos < CAP) {
                g_rows[e][pos] = t;
                g_wt[e][pos]   = wts[k] * inv;
            }
        }
    }
}

// ---------------------------------------------------------------------------
// Kernel 2: fused expert FFN + weighted combine.
// grid = (CAP/ROWT, NE).  block = 256 threads.
// dyn smem: Xs[32][512] | Hs[32][256] | Wa[64][64] | Wb[64][64] | rows/wt
// ---------------------------------------------------------------------------
extern __shared__ float smem[];

__global__ __launch_bounds__(256, 1) void ffn_kernel(
    const float* __restrict__ x,
    const float* __restrict__ w1,
    const float* __restrict__ w3,
    const float* __restrict__ w2,
    float* __restrict__ out)
{
    const int e   = blockIdx.y;
    const int cnt = min(g_count[e], CAP);
    const int r0  = blockIdx.x * ROWT;
    if (r0 >= cnt) return;
    const int nr  = min(ROWT, cnt - r0);

    float* Xs = smem;                         // 32*512
    float* Hs = smem + 32 * 512;              // 32*256
    float* Wa = Hs + 32 * 256;                // 64*64
    float* Wb = Wa + 64 * 64;                 // 64*64
    int*   rows_s = (int*)(Wb + 64 * 64);     // 32
    float* wt_s   = (float*)(rows_s + 32);    // 32

    const int tid = threadIdx.x;
    if (tid < 32) {
        int rr = r0 + tid;
        rows_s[tid] = (tid < nr) ? g_rows[e][rr] : 0;
        wt_s[tid]   = (tid < nr) ? g_wt[e][rr]   : 0.0f;
    }
    __syncthreads();

    // load X tile (zero-padded past nr)
    {
        const float4* x4 = (const float4*)x;
        float4* Xs4 = (float4*)Xs;
        #pragma unroll
        for (int j = 0; j < 16; j++) {
            int idx = j * 256 + tid;          // 4096 float4
            int row = idx >> 7;
            int col = idx & 127;
            float4 v = make_float4(0.f, 0.f, 0.f, 0.f);
            if (row < nr) v = x4[(size_t)rows_s[row] * 128 + col];
            Xs4[idx] = v;
        }
    }

    const int cp = tid & 31;          // col-pair index
    const int rg = tid >> 5;          // row group 0..7 (4 rows each)
    const int c  = cp * 2;

    // ---------- Phase A: H = silu(X@W1) * (X@W3) ----------
    for (int ct = 0; ct < 4; ct++) {
        float a1[4][2] = {}, a3[4][2] = {};
        for (int kc = 0; kc < DIM; kc += 64) {
            __syncthreads();
            const float4* w1g = (const float4*)(w1 + ((size_t)e * DIM + kc) * MOE + ct * 64);
            const float4* w3g = (const float4*)(w3 + ((size_t)e * DIM + kc) * MOE + ct * 64);
            #pragma unroll
            for (int j = 0; j < 4; j++) {
                int idx = j * 256 + tid;      // 1024 float4 per matrix
                int k   = idx >> 4;
                int m4  = idx & 15;
                ((float4*)Wa)[k * 16 + m4] = w1g[(size_t)k * 64 + m4];
                ((float4*)Wb)[k * 16 + m4] = w3g[(size_t)k * 64 + m4];
            }
            __syncthreads();
            #pragma unroll
            for (int kk = 0; kk < 64; kk += 2) {
                float2 wa0 = *(float2*)&Wa[kk * 64 + c];
                float2 wa1 = *(float2*)&Wa[(kk + 1) * 64 + c];
                float2 wb0 = *(float2*)&Wb[kk * 64 + c];
                float2 wb1 = *(float2*)&Wb[(kk + 1) * 64 + c];
                #pragma unroll
                for (int i = 0; i < 4; i++) {
                    float2 xv = *(float2*)&Xs[(rg * 4 + i) * DIM + kc + kk];
                    a1[i][0] += xv.x * wa0.x + xv.y * wa1.x;
                    a1[i][1] += xv.x * wa0.y + xv.y * wa1.y;
                    a3[i][0] += xv.x * wb0.x + xv.y * wb1.x;
                    a3[i][1] += xv.x * wb0.y + xv.y * wb1.y;
                }
            }
        }
        #pragma unroll
        for (int i = 0; i < 4; i++) {
            int row = rg * 4 + i;
            float v0 = a1[i][0], v1 = a1[i][1];
            float h0 = v0 / (1.0f + __expf(-v0)) * a3[i][0];
            float h1 = v1 / (1.0f + __expf(-v1)) * a3[i][1];
            *(float2*)&Hs[row * MOE + ct * 64 + c] = make_float2(h0, h1);
        }
    }
    __syncthreads();

    // ---------- Phase B: Y = H @ W2, weighted atomic combine ----------
    for (int ct = 0; ct < 8; ct++) {
        float acc[4][2] = {};
        for (int kc = 0; kc < MOE; kc += 64) {
            __syncthreads();
            const float4* w2g = (const float4*)(w2 + ((size_t)e * MOE + kc) * DIM + ct * 64);
            #pragma unroll
            for (int j = 0; j < 4; j++) {
                int idx = j * 256 + tid;
                int k   = idx >> 4;
                int m4  = idx & 15;
                ((float4*)Wa)[k * 16 + m4] = w2g[(size_t)k * 128 + m4];
            }
            __syncthreads();
            #pragma unroll
            for (int kk = 0; kk < 64; kk += 2) {
                float2 w0 = *(float2*)&Wa[kk * 64 + c];
                float2 w1v = *(float2*)&Wa[(kk + 1) * 64 + c];
                #pragma unroll
                for (int i = 0; i < 4; i++) {
                    float2 hv = *(float2*)&Hs[(rg * 4 + i) * MOE + kc + kk];
                    acc[i][0] += hv.x * w0.x + hv.y * w1v.x;
                    acc[i][1] += hv.x * w0.y + hv.y * w1v.y;
                }
            }
        }
        #pragma unroll
        for (int i = 0; i < 4; i++) {
            int row = rg * 4 + i;
            if (row < nr) {
                float wgt = wt_s[row];
                float* op = out + (size_t)rows_s[row] * DIM + ct * 64 + c;
                atomicAdd(op,     acc[i][0] * wgt);
                atomicAdd(op + 1, acc[i][1] * wgt);
            }
        }
    }
}

// ---------------------------------------------------------------------------
extern "C" void kernel_launch(void* const* d_in, const int* in_sizes, int n_in,
                              void* d_out, int out_size) {
    const float* x      = (const float*)d_in[0];
    const float* gate_w = (const float*)d_in[1];
    const float* gate_b = (const float*)d_in[2];
    const float* w1     = (const float*)d_in[3];
    const float* w3     = (const float*)d_in[4];
    const float* w2     = (const float*)d_in[5];
    float* out = (float*)d_out;

    static const int FFN_SMEM = (32 * 512 + 32 * 256 + 64 * 64 * 2) * 4 + 32 * 8;
    cudaFuncSetAttribute(ffn_kernel, cudaFuncAttributeMaxDynamicSharedMemorySize, FFN_SMEM);

    zero_kernel<<<(T_TOK * DIM + 255) / 256, 256>>>(out);
    gate_kernel<<<T_TOK, 64>>>(x, gate_w, gate_b);
    dim3 grid(CAP / ROWT, NE);
    ffn_kernel<<<grid, 256, FFN_SMEM>>>(x, w1, w3, w2, out);
}

// round 2
// speedup vs baseline: 1.3898x; 1.3898x over previous
#include <cuda_runtime.h>
#include <math.h>

#define T_TOK 2048
#define DIM   512
#define MOE   256
#define NE    64
#define NG    8
#define TOPKG 4
#define KSEL  8
#define RSCALE 2.5f
#define CAP   1024
#define ROWT  32

__device__ int   g_count[NE];
__device__ int   g_rows[NE][CAP];
__device__ float g_wt[NE][CAP];

#define CP_ASYNC16(smem_u32, gptr) \
    asm volatile("cp.async.cg.shared.global [%0], [%1], 16;\n" :: "r"(smem_u32), "l"(gptr))
#define CP_COMMIT()  asm volatile("cp.async.commit_group;\n" ::: "memory")
#define CP_WAIT0()   asm volatile("cp.async.wait_group 0;\n" ::: "memory")

// ---------------------------------------------------------------------------
// Kernel 0: zero output + expert counters
// ---------------------------------------------------------------------------
__global__ void zero_kernel(float* __restrict__ out) {
    int i = blockIdx.x * blockDim.x + threadIdx.x;
    if (i < T_TOK * DIM) out[i] = 0.0f;
    if (i < NE) g_count[i] = 0;
}

// ---------------------------------------------------------------------------
// Kernel 1: gating. 1 block per token, 64 threads (one per expert).
// ---------------------------------------------------------------------------
__global__ __launch_bounds__(64) void gate_kernel(
    const float* __restrict__ x,
    const float* __restrict__ gate_w,
    const float* __restrict__ gate_b)
{
    __shared__ float xs[DIM];
    __shared__ float gws[64][68];
    __shared__ float scores[NE];
    __shared__ float sb[NE];

    const int t   = blockIdx.x;
    const int tid = threadIdx.x;

    const float4* x4 = (const float4*)(x + (size_t)t * DIM);
    ((float4*)xs)[tid]      = x4[tid];
    ((float4*)xs)[64 + tid] = x4[64 + tid];
    __syncthreads();

    float acc = 0.0f;
    const float4* gw4 = (const float4*)gate_w;
    for (int kc = 0; kc < DIM; kc += 64) {
        __syncthreads();
        #pragma unroll
        for (int j = 0; j < 16; j++) {
            int idx = j * 64 + tid;
            int e   = idx >> 4;
            int m4  = idx & 15;
            *(float4*)&gws[e][m4 * 4] = gw4[(size_t)e * (DIM/4) + (kc >> 2) + m4];
        }
        __syncthreads();
        #pragma unroll
        for (int kk = 0; kk < 64; kk += 4) {
            float4 wv = *(float4*)&gws[tid][kk];
            float4 xv = *(float4*)&xs[kc + kk];
            acc += xv.x * wv.x + xv.y * wv.y + xv.z * wv.z + xv.w * wv.w;
        }
    }
    float sc = 1.0f / (1.0f + expf(-acc));
    scores[tid] = sc;
    sb[tid]     = sc + gate_b[tid];
    __syncthreads();

    if (tid == 0) {
        const float NEG = -3.0e38f;
        float gsc[NG];
        #pragma unroll
        for (int g = 0; g < NG; g++) {
            float m1 = NEG, m2 = NEG;
            #pragma unroll
            for (int j = 0; j < 8; j++) {
                float v = sb[g * 8 + j];
                if (v > m1) { m2 = m1; m1 = v; }
                else if (v > m2) { m2 = v; }
            }
            gsc[g] = m1 + m2;
        }
        bool gsel[NG];
        #pragma unroll
        for (int g = 0; g < NG; g++) gsel[g] = false;
        for (int it = 0; it < TOPKG; it++) {
            int bg = -1; float bv = NEG;
            #pragma unroll
            for (int g = 0; g < NG; g++)
                if (!gsel[g] && gsc[g] > bv) { bv = gsc[g]; bg = g; }
            gsel[bg] = true;
        }
        for (int e = 0; e < NE; e++)
            if (!gsel[e >> 3]) sb[e] = NEG;
        int   idxs[KSEL];
        float wts[KSEL];
        float wsum = 0.0f;
        for (int k = 0; k < KSEL; k++) {
            int bi = 0; float bv = NEG;
            for (int e = 0; e < NE; e++)
                if (sb[e] > bv) { bv = sb[e]; bi = e; }
            sb[bi] = NEG;
            idxs[k] = bi;
            wts[k]  = scores[bi];
            wsum   += wts[k];
        }
        float inv = RSCALE / wsum;
        for (int k = 0; k < KSEL; k++) {
            int e = idxs[k];
            int pos = atomicAdd(&g_count[e], 1);
            if (pos < CAP) {
                g_rows[e][pos] = t;
                g_wt[e][pos]   = wts[k] * inv;
            }
        }
    }
}

// ---------------------------------------------------------------------------
// Kernel 2: fused expert FFN + weighted combine.
// grid = (CAP/ROWT, NE), block = 256.
// smem: Xs[32][512] | Hs[32][256] | W1b[2][64][128] | W3b[2][64][128] | rows/wt
// (phase B reuses W1b for w2 panels)
// ---------------------------------------------------------------------------
extern __shared__ float smem[];

// stage one 64x128 fp32 panel (row stride `stride` floats) via cp.async
__device__ __forceinline__ void stage_panel(const float* __restrict__ g,
                                            float* __restrict__ s,
                                            int stride, int tid) {
    #pragma unroll
    for (int j = 0; j < 8; j++) {
        int idx = j * 256 + tid;           // 2048 float4
        int k   = idx >> 5;
        int m4  = idx & 31;
        unsigned sa = (unsigned)__cvta_generic_to_shared(s + k * 128 + m4 * 4);
        CP_ASYNC16(sa, g + (size_t)k * stride + m4 * 4);
    }
}

__global__ __launch_bounds__(256, 1) void ffn_kernel(
    const float* __restrict__ x,
    const float* __restrict__ w1,
    const float* __restrict__ w3,
    const float* __restrict__ w2,
    float* __restrict__ out)
{
    const int e   = blockIdx.y;
    const int cnt = min(g_count[e], CAP);
    const int r0  = blockIdx.x * ROWT;
    if (r0 >= cnt) return;
    const int nr  = min(ROWT, cnt - r0);

    float* Xs  = smem;                        // 32*512
    float* Hs  = Xs + 32 * 512;               // 32*256
    float* W1b = Hs + 32 * 256;               // 2*64*128
    float* W3b = W1b + 2 * 64 * 128;          // 2*64*128
    int*   rows_s = (int*)(W3b + 2 * 64 * 128);
    float* wt_s   = (float*)(rows_s + 32);

    const int tid = threadIdx.x;
    if (tid < 32) {
        int rr = r0 + tid;
        rows_s[tid] = (tid < nr) ? g_rows[e][rr] : 0;
        wt_s[tid]   = (tid < nr) ? g_wt[e][rr]   : 0.0f;
    }
    __syncthreads();

    // load X tile (zero-padded past nr)
    {
        const float4* x4 = (const float4*)x;
        float4* Xs4 = (float4*)Xs;
        #pragma unroll
        for (int j = 0; j < 16; j++) {
            int idx = j * 256 + tid;          // 4096 float4
            int row = idx >> 7;
            int col = idx & 127;
            float4 v = make_float4(0.f, 0.f, 0.f, 0.f);
            if (row < nr) v = x4[(size_t)rows_s[row] * 128 + col];
            Xs4[idx] = v;
        }
    }
    __syncthreads();

    const int cg = tid & 31;          // col group (4 cols)
    const int rg = tid >> 5;          // row group (4 rows)
    const int c  = cg * 4;

    // ---------- Phase A: H = silu(X@W1) * (X@W3), col tiles of 128 ----------
    for (int ct = 0; ct < 2; ct++) {
        const float* w1g = w1 + (size_t)e * DIM * MOE + ct * 128;
        const float* w3g = w3 + (size_t)e * DIM * MOE + ct * 128;
        float a1[4][4] = {}, a3[4][4] = {};

        stage_panel(w1g, W1b, MOE, tid);
        stage_panel(w3g, W3b, MOE, tid);
        CP_COMMIT();

        for (int kci = 0; kci < 8; kci++) {
            CP_WAIT0();
            __syncthreads();
            if (kci < 7) {
                int nb = (kci + 1) & 1;
                stage_panel(w1g + (size_t)(kci + 1) * 64 * MOE, W1b + nb * 64 * 128, MOE, tid);
                stage_panel(w3g + (size_t)(kci + 1) * 64 * MOE, W3b + nb * 64 * 128, MOE, tid);
                CP_COMMIT();
            }
            const float* Wa = W1b + (kci & 1) * 64 * 128;
            const float* Wb = W3b + (kci & 1) * 64 * 128;
            const int kc = kci * 64;
            #pragma unroll 8
            for (int kk = 0; kk < 64; kk += 2) {
                float4 wa0 = *(const float4*)&Wa[kk * 128 + c];
                float4 wa1 = *(const float4*)&Wa[(kk + 1) * 128 + c];
                float4 wb0 = *(const float4*)&Wb[kk * 128 + c];
                float4 wb1 = *(const float4*)&Wb[(kk + 1) * 128 + c];
                #pragma unroll
                for (int i = 0; i < 4; i++) {
                    float2 xv = *(const float2*)&Xs[(rg * 4 + i) * DIM + kc + kk];
                    a1[i][0] += xv.x * wa0.x + xv.y * wa1.x;
                    a1[i][1] += xv.x * wa0.y + xv.y * wa1.y;
                    a1[i][2] += xv.x * wa0.z + xv.y * wa1.z;
                    a1[i][3] += xv.x * wa0.w + xv.y * wa1.w;
                    a3[i][0] += xv.x * wb0.x + xv.y * wb1.x;
                    a3[i][1] += xv.x * wb0.y + xv.y * wb1.y;
                    a3[i][2] += xv.x * wb0.z + xv.y * wb1.z;
                    a3[i][3] += xv.x * wb0.w + xv.y * wb1.w;
                }
            }
        }
        // SwiGLU -> Hs (each thread owns its 4x4 region, no race)
        #pragma unroll
        for (int i = 0; i < 4; i++) {
            int row = rg * 4 + i;
            float4 h;
            float v0 = a1[i][0], v1 = a1[i][1], v2 = a1[i][2], v3 = a1[i][3];
            h.x = v0 / (1.0f + __expf(-v0)) * a3[i][0];
            h.y = v1 / (1.0f + __expf(-v1)) * a3[i][1];
            h.z = v2 / (1.0f + __expf(-v2)) * a3[i][2];
            h.w = v3 / (1.0f + __expf(-v3)) * a3[i][3];
            *(float4*)&Hs[row * MOE + ct * 128 + c] = h;
        }
    }
    __syncthreads();   // Hs complete before phase B reads it

    // ---------- Phase B: Y = H @ W2, col tiles of 128 over DIM ----------
    for (int ct = 0; ct < 4; ct++) {
        const float* w2g = w2 + (size_t)e * MOE * DIM + ct * 128;
        float acc[4][4] = {};

        stage_panel(w2g, W1b, DIM, tid);
        CP_COMMIT();

        for (int kci = 0; kci < 4; kci++) {
            CP_WAIT0();
            __syncthreads();
            if (kci < 3) {
                int nb = (kci + 1) & 1;
                stage_panel(w2g + (size_t)(kci + 1) * 64 * DIM, W1b + nb * 64 * 128, DIM, tid);
                CP_COMMIT();
            }
            const float* Wc = W1b + (kci & 1) * 64 * 128;
            const int kc = kci * 64;
            #pragma unroll 8
            for (int kk = 0; kk < 64; kk += 2) {
                float4 w0 = *(const float4*)&Wc[kk * 128 + c];
                float4 w1v = *(const float4*)&Wc[(kk + 1) * 128 + c];
                #pragma unroll
                for (int i = 0; i < 4; i++) {
                    float2 hv = *(const float2*)&Hs[(rg * 4 + i) * MOE + kc + kk];
                    acc[i][0] += hv.x * w0.x + hv.y * w1v.x;
                    acc[i][1] += hv.x * w0.y + hv.y * w1v.y;
                    acc[i][2] += hv.x * w0.z + hv.y * w1v.z;
                    acc[i][3] += hv.x * w0.w + hv.y * w1v.w;
                }
            }
        }
        #pragma unroll
        for (int i = 0; i < 4; i++) {
            int row = rg * 4 + i;
            if (row < nr) {
                float wgt = wt_s[row];
                float* op = out + (size_t)rows_s[row] * DIM + ct * 128 + c;
                atomicAdd(op,     acc[i][0] * wgt);
                atomicAdd(op + 1, acc[i][1] * wgt);
                atomicAdd(op + 2, acc[i][2] * wgt);
                atomicAdd(op + 3, acc[i][3] * wgt);
            }
        }
    }
}

// ---------------------------------------------------------------------------
extern "C" void kernel_launch(void* const* d_in, const int* in_sizes, int n_in,
                              void* d_out, int out_size) {
    const float* x      = (const float*)d_in[0];
    const float* gate_w = (const float*)d_in[1];
    const float* gate_b = (const float*)d_in[2];
    const float* w1     = (const float*)d_in[3];
    const float* w3     = (const float*)d_in[4];
    const float* w2     = (const float*)d_in[5];
    float* out = (float*)d_out;

    static const int FFN_SMEM = (32 * 512 + 32 * 256 + 2 * 64 * 128 * 2) * 4 + 32 * 8;
    cudaFuncSetAttribute(ffn_kernel, cudaFuncAttributeMaxDynamicSharedMemorySize, FFN_SMEM);

    zero_kernel<<<(T_TOK * DIM + 255) / 256, 256>>>(out);
    gate_kernel<<<T_TOK, 64>>>(x, gate_w, gate_b);
    dim3 grid(CAP / ROWT, NE);
    ffn_kernel<<<grid, 256, FFN_SMEM>>>(x, w1, w3, w2, out);
}

// round 4
// speedup vs baseline: 2.2879x; 1.6462x over previous
#include <cuda_runtime.h>
#include <stdint.h>
#include <math.h>

#define T_TOK 2048
#define DIM   512
#define MOE   256
#define NE    64
#define NG    8
#define TOPKG 4
#define KSEL  8
#define RSCALE 2.5f
#define CAP   1024
#define ROWT  64
#define THREADS 512

__device__ int   g_count[NE];
__device__ int   g_rows[NE][CAP];
__device__ float g_wt[NE][CAP];

// ---------------------------------------------------------------------------
// smem word-offset map (uint32 words)
//  [0,64)    rows_s          [64,128) wt_s
//  XB: X frag buffers, 2 x 1056 words  (blocks (s,mt): pitch 132)
//  WB: phase A: W1[2 bufs x 4352] then W3[2 x 4352]  (blocks (s*32+n8): pitch 68)
//      phase B: W2 [2 bufs x 8704]                    (blocks (s*64+n8): pitch 68)
//  HB: H frags, 32s x 4mt blocks, pitch 132 = 16896 words
// ---------------------------------------------------------------------------
#define XB       128
#define XBUF_W   1056
#define WB       2240
#define WA_BUF   4352
#define WA_MAT   8704
#define WB_BUF   8704
#define HB       19648
#define SMEM_W   36544
#define FFN_SMEM (SMEM_W * 4)

__device__ __forceinline__ uint32_t f2tf(float f) {
    uint32_t r;
    asm("cvt.rna.tf32.f32 %0, %1;" : "=r"(r) : "f"(f));
    return r;
}
__device__ __forceinline__ uint4 cvt4(float4 w) {
    return make_uint4(f2tf(w.x), f2tf(w.y), f2tf(w.z), f2tf(w.w));
}
__device__ __forceinline__ void mma8(float* d, const uint32_t* a,
                                     uint32_t b0, uint32_t b1) {
    asm volatile(
        "mma.sync.aligned.m16n8k8.row.col.f32.tf32.tf32.f32 "
        "{%0,%1,%2,%3}, {%4,%5,%6,%7}, {%8,%9}, {%0,%1,%2,%3};"
        : "+f"(d[0]), "+f"(d[1]), "+f"(d[2]), "+f"(d[3])
        : "r"(a[0]), "r"(a[1]), "r"(a[2]), "r"(a[3]), "r"(b0), "r"(b1));
}

// ---------------------------------------------------------------------------
__global__ void zero_kernel(float4* __restrict__ out) {
    int i = blockIdx.x * blockDim.x + threadIdx.x;
    if (i < T_TOK * DIM / 4) out[i] = make_float4(0.f, 0.f, 0.f, 0.f);
    if (i < NE) g_count[i] = 0;
}

// ---------------------------------------------------------------------------
// gating (unchanged, known-good)
// ---------------------------------------------------------------------------
__global__ __launch_bounds__(64) void gate_kernel(
    const float* __restrict__ x,
    const float* __restrict__ gate_w,
    const float* __restrict__ gate_b)
{
    __shared__ float xs[DIM];
    __shared__ float gws[64][68];
    __shared__ float scores[NE];
    __shared__ float sb[NE];

    const int t   = blockIdx.x;
    const int tid = threadIdx.x;

    const float4* x4 = (const float4*)(x + (size_t)t * DIM);
    ((float4*)xs)[tid]      = x4[tid];
    ((float4*)xs)[64 + tid] = x4[64 + tid];
    __syncthreads();

    float acc = 0.0f;
    const float4* gw4 = (const float4*)gate_w;
    for (int kc = 0; kc < DIM; kc += 64) {
        __syncthreads();
        #pragma unroll
        for (int j = 0; j < 16; j++) {
            int idx = j * 64 + tid;
            int e   = idx >> 4;
            int m4  = idx & 15;
            *(float4*)&gws[e][m4 * 4] = gw4[(size_t)e * (DIM/4) + (kc >> 2) + m4];
        }
        __syncthreads();
        #pragma unroll
        for (int kk = 0; kk < 64; kk += 4) {
            float4 wv = *(float4*)&gws[tid][kk];
            float4 xv = *(float4*)&xs[kc + kk];
            acc += xv.x * wv.x + xv.y * wv.y + xv.z * wv.z + xv.w * wv.w;
        }
    }
    float sc = 1.0f / (1.0f + expf(-acc));
    scores[tid] = sc;
    sb[tid]     = sc + gate_b[tid];
    __syncthreads();

    if (tid == 0) {
        const float NEG = -3.0e38f;
        float gsc[NG];
        #pragma unroll
        for (int g = 0; g < NG; g++) {
            float m1 = NEG, m2 = NEG;
            #pragma unroll
            for (int j = 0; j < 8; j++) {
                float v = sb[g * 8 + j];
                if (v > m1) { m2 = m1; m1 = v; }
                else if (v > m2) { m2 = v; }
            }
            gsc[g] = m1 + m2;
        }
        bool gsel[NG];
        #pragma unroll
        for (int g = 0; g < NG; g++) gsel[g] = false;
        for (int it = 0; it < TOPKG; it++) {
            int bg = -1; float bv = NEG;
            #pragma unroll
            for (int g = 0; g < NG; g++)
                if (!gsel[g] && gsc[g] > bv) { bv = gsc[g]; bg = g; }
            gsel[bg] = true;
        }
        for (int e = 0; e < NE; e++)
            if (!gsel[e >> 3]) sb[e] = NEG;
        int   idxs[KSEL];
        float wts[KSEL];
        float wsum = 0.0f;
        for (int k = 0; k < KSEL; k++) {
            int bi = 0; float bv = NEG;
            for (int e = 0; e < NE; e++)
                if (sb[e] > bv) { bv = sb[e]; bi = e; }
            sb[bi] = NEG;
            idxs[k] = bi;
            wts[k]  = scores[bi];
            wsum   += wts[k];
        }
        float inv = RSCALE / wsum;
        for (int k = 0; k < KSEL; k++) {
            int e = idxs[k];
            int pos = atomicAdd(&g_count[e], 1);
            if (pos < CAP) {
                g_rows[e][pos] = t;
                g_wt[e][pos]   = wts[k] * inv;
            }
        }
    }
}

// ---------------------------------------------------------------------------
// FFN via mma.sync tf32.  grid=(CAP/64, NE), 512 threads (16 warps).
// Warps: mg = wid>>3 (m-half, 32 rows), nw = wid&7 (n-slice).
// Fragment-order smem planes; double-buffered k16 weight/X chunks.
// ---------------------------------------------------------------------------
__global__ __launch_bounds__(THREADS, 1) void ffn_mma_kernel(
    const float* __restrict__ x,
    const float* __restrict__ w1,
    const float* __restrict__ w3,
    const float* __restrict__ w2,
    float* __restrict__ out)
{
    extern __shared__ uint32_t sm[];
    const int e   = blockIdx.y;
    const int cnt = min(g_count[e], CAP);
    const int r0  = blockIdx.x * ROWT;
    if (r0 >= cnt) return;
    const int nr  = min(ROWT, cnt - r0);

    const int tid  = threadIdx.x;
    const int lane = tid & 31, wid = tid >> 5;
    const int g    = lane >> 2, tig = lane & 3;
    const int perm = tig * 8 + g;            // B-frag plane permutation
    const int mg   = wid >> 3, nw = wid & 7;

    int*   rows_s = (int*)sm;
    float* wt_s   = (float*)(sm + 64);
    if (tid < ROWT) {
        rows_s[tid] = (tid < nr) ? g_rows[e][r0 + tid] : 0;
        wt_s[tid]   = (tid < nr) ? g_wt[e][r0 + tid]   : 0.0f;
    }
    __syncthreads();

    // ---- staging index precompute (per-thread, constant) ----
    // X: thread -> (row, 2 k-floats). row = tid>>3, q = tid&7, k = c*16 + 2q..2q+1
    const int xrow = tid >> 3, xq = tid & 7;
    const int xs_   = xq >> 2;                     // k8 index within chunk
    const int xtig  = (xq & 1) * 2;                // kk&3 (even)
    const int xka   = (xq & 3) >> 1;               // kk>>2
    const int xmt   = xrow >> 4;
    const int xg    = xrow & 7;
    const int xreg  = ((xrow & 15) >> 3) + 2 * xka;
    const int xword = XB + (xs_ * 4 + xmt) * 132 + xreg * 32 + xg * 4 + xtig;
    const float2* x2 = (const float2*)x;
    const size_t xgidx = (size_t)rows_s[xrow] * (DIM / 2) + xq;

    // W (both phases): k-row = wid (0..15), n-chunk = lane
    const int ws_   = wid >> 3;                    // k8 index within chunk
    const int wtig  = wid & 3;
    const int wreg  = (wid & 7) >> 2;
    const int wbaseA = (ws_ * 32 + lane) * 68 + wreg * 32 + wtig * 8;   // n8 = lane
    const float4* w1g4 = (const float4*)(w1 + (size_t)e * DIM * MOE);
    const float4* w3g4 = (const float4*)(w3 + (size_t)e * DIM * MOE);
    const float4* w2g4 = (const float4*)(w2 + (size_t)e * MOE * DIM);

    // =================== Phase A: a1/a3 = X @ W1 / X @ W3 ===================
    float accA[2][4][2][4] = {};   // [mat][n8 j][m tile][reg]

    // prologue: stage chunk 0 into buf 0
    {
        float2 v = x2[xgidx];
        *(uint2*)&sm[xword] = make_uint2(f2tf(v.x), f2tf(v.y));
        #pragma unroll
        for (int i = 0; i < 2; i++) {
            float4 a = w1g4[(size_t)wid * 64 + lane * 2 + i];
            float4 b = w3g4[(size_t)wid * 64 + lane * 2 + i];
            *(uint4*)&sm[WB + wbaseA + i * 4]          = cvt4(a);
            *(uint4*)&sm[WB + WA_MAT + wbaseA + i * 4] = cvt4(b);
        }
    }
    __syncthreads();

    for (int c = 0; c < 32; c++) {
        const int buf = c & 1;
        float2 px; float4 pw1[2], pw3[2];
        const bool pf = (c < 31);
        if (pf) {
            px = x2[xgidx + (size_t)(c + 1) * 8];
            #pragma unroll
            for (int i = 0; i < 2; i++) {
                size_t gi = ((size_t)(c + 1) * 16 + wid) * 64 + lane * 2 + i;
                pw1[i] = w1g4[gi];
                pw3[i] = w3g4[gi];
            }
        }
        #pragma unroll
        for (int s = 0; s < 2; s++) {
            uint32_t a[2][4];
            const int ab = XB + buf * XBUF_W + (s * 4 + mg * 2) * 132 + lane;
            #pragma unroll
            for (int r = 0; r < 4; r++) {
                a[0][r] = sm[ab + r * 32];
                a[1][r] = sm[ab + 132 + r * 32];
            }
            #pragma unroll
            for (int mat = 0; mat < 2; mat++) {
                const int wb0 = WB + mat * WA_MAT + buf * WA_BUF +
                                (s * 32 + nw * 4) * 68 + perm;
                #pragma unroll
                for (int j = 0; j < 4; j++) {
                    uint32_t b0 = sm[wb0 + j * 68];
                    uint32_t b1 = sm[wb0 + j * 68 + 32];
                    mma8(accA[mat][j][0], a[0], b0, b1);
                    mma8(accA[mat][j][1], a[1], b0, b1);
                }
            }
        }
        if (pf) {
            const int db = buf ^ 1;
            *(uint2*)&sm[xword + db * XBUF_W] = make_uint2(f2tf(px.x), f2tf(px.y));
            #pragma unroll
            for (int i = 0; i < 2; i++) {
                *(uint4*)&sm[WB + db * WA_BUF + wbaseA + i * 4]          = cvt4(pw1[i]);
                *(uint4*)&sm[WB + WA_MAT + db * WA_BUF + wbaseA + i * 4] = cvt4(pw3[i]);
            }
        }
        __syncthreads();
    }

    // ========== SwiGLU -> H fragment planes (A-frag layout for phase B) =====
    #pragma unroll
    for (int j = 0; j < 4; j++) {
        #pragma unroll
        for (int m = 0; m < 2; m++) {
            #pragma unroll
            for (int r = 0; r < 4; r++) {
                float v1 = accA[0][j][m][r];
                float v3 = accA[1][j][m][r];
                float h  = v1 / (1.0f + __expf(-v1)) * v3;
                int rhalf = r >> 1, jb = r & 1;
                int hcol  = nw * 32 + j * 8 + tig * 2 + jb;
                int sH    = hcol >> 3;
                int kk2   = hcol & 7;
                int reg2  = rhalf + 2 * (kk2 >> 2);
                sm[HB + (sH * 4 + mg * 2 + m) * 132 + reg2 * 32 + g * 4 + (kk2 & 3)]
                    = f2tf(h);
            }
        }
    }
    __syncthreads();

    // =================== Phase B: Y = H @ W2 ================================
    float accB[8][2][4] = {};   // [n8 j][m tile][reg]

    // prologue: stage W2 chunk 0 into buf 0
    {
        #pragma unroll
        for (int i = 0; i < 4; i++) {
            float4 w = w2g4[(size_t)wid * 128 + lane * 4 + i];
            int n8 = lane * 2 + (i >> 1);
            *(uint4*)&sm[WB + (ws_ * 64 + n8) * 68 + wreg * 32 + wtig * 8 + (i & 1) * 4]
                = cvt4(w);
        }
    }
    __syncthreads();

    for (int c = 0; c < 16; c++) {
        const int buf = c & 1;
        float4 pw2[4];
        const bool pf = (c < 15);
        if (pf) {
            #pragma unroll
            for (int i = 0; i < 4; i++)
                pw2[i] = w2g4[((size_t)(c + 1) * 16 + wid) * 128 + lane * 4 + i];
        }
        #pragma unroll
        for (int s = 0; s < 2; s++) {
            const int sH = c * 2 + s;
            uint32_t a[2][4];
            const int ab = HB + (sH * 4 + mg * 2) * 132 + lane;
            #pragma unroll
            for (int r = 0; r < 4; r++) {
                a[0][r] = sm[ab + r * 32];
                a[1][r] = sm[ab + 132 + r * 32];
            }
            const int wb0 = WB + buf * WB_BUF + (s * 64 + nw * 8) * 68 + perm;
            #pragma unroll
            for (int j = 0; j < 8; j++) {
                uint32_t b0 = sm[wb0 + j * 68];
                uint32_t b1 = sm[wb0 + j * 68 + 32];
                mma8(accB[j][0], a[0], b0, b1);
                mma8(accB[j][1], a[1], b0, b1);
            }
        }
        if (pf) {
            const int db = buf ^ 1;
            #pragma unroll
            for (int i = 0; i < 4; i++) {
                int n8 = lane * 2 + (i >> 1);
                *(uint4*)&sm[WB + db * WB_BUF + (ws_ * 64 + n8) * 68 +
                             wreg * 32 + wtig * 8 + (i & 1) * 4] = cvt4(pw2[i]);
            }
        }
        __syncthreads();
    }

    // =================== Epilogue: weighted atomic combine ==================
    #pragma unroll
    for (int m = 0; m < 2; m++) {
        #pragma unroll
        for (int rh = 0; rh < 2; rh++) {
            int row = mg * 32 + m * 16 + g + 8 * rh;
            if (row < nr) {
                float wgt = wt_s[row];
                float* op = out + (size_t)rows_s[row] * DIM;
                #pragma unroll
                for (int j = 0; j < 8; j++) {
                    int col = nw * 64 + j * 8 + tig * 2;
                    atomicAdd(op + col,     accB[j][m][rh * 2]     * wgt);
                    atomicAdd(op + col + 1, accB[j][m][rh * 2 + 1] * wgt);
                }
            }
        }
    }
}

// ---------------------------------------------------------------------------
extern "C" void kernel_launch(void* const* d_in, const int* in_sizes, int n_in,
                              void* d_out, int out_size) {
    const float* x      = (const float*)d_in[0];
    const float* gate_w = (const float*)d_in[1];
    const float* gate_b = (const float*)d_in[2];
    const float* w1     = (const float*)d_in[3];
    const float* w3     = (const float*)d_in[4];
    const float* w2     = (const float*)d_in[5];
    float* out = (float*)d_out;

    cudaFuncSetAttribute(ffn_mma_kernel, cudaFuncAttributeMaxDynamicSharedMemorySize, FFN_SMEM);

    zero_kernel<<<(T_TOK * DIM / 4 + 255) / 256, 256>>>((float4*)out);
    gate_kernel<<<T_TOK, 64>>>(x, gate_w, gate_b);
    dim3 grid(CAP / ROWT, NE);
    ffn_mma_kernel<<<grid, THREADS, FFN_SMEM>>>(x, w1, w3, w2, out);
}

// round 5
// speedup vs baseline: 3.4059x; 1.4887x over previous
#include <cuda_runtime.h>
#include <stdint.h>
#include <math.h>

#define T_TOK 2048
#define DIM   512
#define MOE   256
#define NE    64
#define NG    8
#define TOPKG 4
#define KSEL  8
#define RSCALE 2.5f
#define CAP   1024
#define ROWT  64
#define THREADS 512

__device__ int   g_count[NE];
__device__ int   g_rows[NE][CAP];
__device__ float g_wt[NE][CAP];

// tf32 panel scratch (fragment order) + converted x
#define WWORDS (NE * DIM * MOE)          // 8388608 words per weight tensor
__device__ uint32_t g_w1t[WWORDS];
__device__ uint32_t g_w3t[WWORDS];
__device__ uint32_t g_w2t[WWORDS];
__device__ uint32_t g_xt[T_TOK * DIM];

// ---------------------------------------------------------------------------
// smem word map (ffn):
//  [0,64) rows_s  [64,128) wt_s
//  stage ring base 128: phase A stride 9760 (W1 4352 | W3 4352 | X 1056), x4
//                       phase B stride 8704 (W2), x4 (overlaid)
//  HB at 39168: 128 blocks x 132 words = 16896
// ---------------------------------------------------------------------------
#define STAGE_BASE 128
#define STA   9760
#define STB   8704
#define XSUB  8704
#define HBW   39168
#define SMEM_W (39168 + 16896)
#define FFN_SMEM (SMEM_W * 4)

#define CP16(dst_b, src) \
    asm volatile("cp.async.cg.shared.global [%0], [%1], 16;" :: "r"(dst_b), "l"(src))
#define CP8(dst_b, src) \
    asm volatile("cp.async.ca.shared.global [%0], [%1], 8;" :: "r"(dst_b), "l"(src))
#define CP_COMMIT() asm volatile("cp.async.commit_group;" ::: "memory")
#define CP_WAIT2()  asm volatile("cp.async.wait_group 2;" ::: "memory")
#define CP_WAIT0()  asm volatile("cp.async.wait_group 0;" ::: "memory")

__device__ __forceinline__ uint32_t f2tf(float f) {
    uint32_t r;
    asm("cvt.rna.tf32.f32 %0, %1;" : "=r"(r) : "f"(f));
    return r;
}
__device__ __forceinline__ uint4 cvt4(float4 w) {
    return make_uint4(f2tf(w.x), f2tf(w.y), f2tf(w.z), f2tf(w.w));
}
__device__ __forceinline__ void mma8(float* d, const uint32_t* a,
                                     uint32_t b0, uint32_t b1) {
    asm volatile(
        "mma.sync.aligned.m16n8k8.row.col.f32.tf32.tf32.f32 "
        "{%0,%1,%2,%3}, {%4,%5,%6,%7}, {%8,%9}, {%0,%1,%2,%3};"
        : "+f"(d[0]), "+f"(d[1]), "+f"(d[2]), "+f"(d[3])
        : "r"(a[0]), "r"(a[1]), "r"(a[2]), "r"(a[3]), "r"(b0), "r"(b1));
}

// ---------------------------------------------------------------------------
// prep kernel: convert weights -> tf32 fragment panels, x -> tf32, zero out,
// zero counters.  One float4 per thread.
// Panel word w encodes: k_local kk (0..15): w = ((kk>>2)&1)*32 + (kk&3)*8 + (n&7)
// ---------------------------------------------------------------------------
#define WQ 2097152          // float4 per weight tensor
#define XQ (T_TOK * DIM / 4)
#define PREP_TOTAL (3 * WQ + 2 * XQ)

__global__ void prep_kernel(const float4* __restrict__ w1,
                            const float4* __restrict__ w3,
                            const float4* __restrict__ w2,
                            const float4* __restrict__ x,
                            float4* __restrict__ out)
{
    unsigned i = blockIdx.x * blockDim.x + threadIdx.x;
    if (i < NE) g_count[i] = 0;
    if (i >= PREP_TOTAL) return;

    if (i < 2 * WQ) {                       // w1 / w3
        const float4* src = (i < WQ) ? w1 : w3;
        uint32_t*     dstb = (i < WQ) ? g_w1t : g_w3t;
        unsigned j = (i < WQ) ? i : i - WQ;
        unsigned elem = j * 4;
        unsigned e = elem >> 17, r = elem & 131071;
        unsigned k = r >> 8, n = r & 255;
        unsigned kk = k & 15, c = k >> 4, s = kk >> 3;
        unsigned w = ((kk >> 2) & 1) * 32 + (kk & 3) * 8 + (n & 7);
        unsigned dst = e * 131072 + c * 4096 + (s * 32 + (n >> 3)) * 64 + w;
        *(uint4*)&dstb[dst] = cvt4(src[j]);
    } else if (i < 3 * WQ) {                // w2
        unsigned j = i - 2 * WQ;
        unsigned elem = j * 4;
        unsigned e = elem >> 17, r = elem & 131071;
        unsigned k = r >> 9, n = r & 511;
        unsigned kk = k & 15, c = k >> 4, s = kk >> 3;
        unsigned w = ((kk >> 2) & 1) * 32 + (kk & 3) * 8 + (n & 7);
        unsigned dst = e * 131072 + c * 8192 + (s * 64 + (n >> 3)) * 64 + w;
        *(uint4*)&g_w2t[dst] = cvt4(w2[j]);
    } else if (i < 3 * WQ + XQ) {           // x -> tf32
        unsigned j = i - 3 * WQ;
        *(uint4*)&g_xt[j * 4] = cvt4(x[j]);
    } else {                                // zero out
        out[i - 3 * WQ - XQ] = make_float4(0.f, 0.f, 0.f, 0.f);
    }
}

// ---------------------------------------------------------------------------
// gating (unchanged, known-good)
// ---------------------------------------------------------------------------
__global__ __launch_bounds__(64) void gate_kernel(
    const float* __restrict__ x,
    const float* __restrict__ gate_w,
    const float* __restrict__ gate_b)
{
    __shared__ float xs[DIM];
    __shared__ float gws[64][68];
    __shared__ float scores[NE];
    __shared__ float sb[NE];

    const int t   = blockIdx.x;
    const int tid = threadIdx.x;

    const float4* x4 = (const float4*)(x + (size_t)t * DIM);
    ((float4*)xs)[tid]      = x4[tid];
    ((float4*)xs)[64 + tid] = x4[64 + tid];
    __syncthreads();

    float acc = 0.0f;
    const float4* gw4 = (const float4*)gate_w;
    for (int kc = 0; kc < DIM; kc += 64) {
        __syncthreads();
        #pragma unroll
        for (int j = 0; j < 16; j++) {
            int idx = j * 64 + tid;
            int e   = idx >> 4;
            int m4  = idx & 15;
            *(float4*)&gws[e][m4 * 4] = gw4[(size_t)e * (DIM/4) + (kc >> 2) + m4];
        }
        __syncthreads();
        #pragma unroll
        for (int kk = 0; kk < 64; kk += 4) {
            float4 wv = *(float4*)&gws[tid][kk];
            float4 xv = *(float4*)&xs[kc + kk];
            acc += xv.x * wv.x + xv.y * wv.y + xv.z * wv.z + xv.w * wv.w;
        }
    }
    float sc = 1.0f / (1.0f + expf(-acc));
    scores[tid] = sc;
    sb[tid]     = sc + gate_b[tid];
    __syncthreads();

    if (tid == 0) {
        const float NEG = -3.0e38f;
        float gsc[NG];
        #pragma unroll
        for (int g = 0; g < NG; g++) {
            float m1 = NEG, m2 = NEG;
            #pragma unroll
            for (int j = 0; j < 8; j++) {
                float v = sb[g * 8 + j];
                if (v > m1) { m2 = m1; m1 = v; }
                else if (v > m2) { m2 = v; }
            }
            gsc[g] = m1 + m2;
        }
        bool gsel[NG];
        #pragma unroll
        for (int g = 0; g < NG; g++) gsel[g] = false;
        for (int it = 0; it < TOPKG; it++) {
            int bg = -1; float bv = NEG;
            #pragma unroll
            for (int g = 0; g < NG; g++)
                if (!gsel[g] && gsc[g] > bv) { bv = gsc[g]; bg = g; }
            gsel[bg] = true;
        }
        for (int e = 0; e < NE; e++)
            if (!gsel[e >> 3]) sb[e] = NEG;
        int   idxs[KSEL];
        float wts[KSEL];
        float wsum = 0.0f;
        for (int k = 0; k < KSEL; k++) {
            int bi = 0; float bv = NEG;
            for (int e = 0; e < NE; e++)
                if (sb[e] > bv) { bv = sb[e]; bi = e; }
            sb[bi] = NEG;
            idxs[k] = bi;
            wts[k]  = scores[bi];
            wsum   += wts[k];
        }
        float inv = RSCALE / wsum;
        for (int k = 0; k < KSEL; k++) {
            int e = idxs[k];
            int pos = atomicAdd(&g_count[e], 1);
            if (pos < CAP) {
                g_rows[e][pos] = t;
                g_wt[e][pos]   = wts[k] * inv;
            }
        }
    }
}

// ---------------------------------------------------------------------------
// FFN: mma.sync tf32, cp.async 4-stage pipeline from pre-converted panels.
// grid=(CAP/64, NE), 512 threads.
// ---------------------------------------------------------------------------
__global__ __launch_bounds__(THREADS, 1) void ffn_mma_kernel(
    float* __restrict__ out)
{
    extern __shared__ uint32_t sm[];
    const int e   = blockIdx.y;
    const int cnt = min(g_count[e], CAP);
    const int r0  = blockIdx.x * ROWT;
    if (r0 >= cnt) return;
    const int nr  = min(ROWT, cnt - r0);

    const int tid  = threadIdx.x;
    const int lane = tid & 31, wid = tid >> 5;
    const int g    = lane >> 2, tig = lane & 3;
    const int perm = tig * 8 + g;
    const int mg   = wid >> 3, nw = wid & 7;

    int*   rows_s = (int*)sm;
    float* wt_s   = (float*)(sm + 64);
    if (tid < ROWT) {
        rows_s[tid] = (tid < nr) ? g_rows[e][r0 + tid] : 0;
        wt_s[tid]   = (tid < nr) ? g_wt[e][r0 + tid]   : 0.0f;
    }
    __syncthreads();

    uint32_t smem_b;
    asm("{ .reg .u64 t; cvta.to.shared.u64 t, %1; cvt.u32.u64 %0, t; }"
        : "=r"(smem_b) : "l"(sm));

    // X staging constants (thread -> frag slot)
    const int xrow = tid >> 3, xq = tid & 7;
    const int xs_  = xq >> 2;
    const int xtig = (xq & 1) * 2;
    const int xka  = (xq & 3) >> 1;
    const int xmt  = xrow >> 4;
    const int xg   = xrow & 7;
    const int xreg = ((xrow & 15) >> 3) + 2 * xka;
    const int xword = (xs_ * 4 + xmt) * 132 + xreg * 32 + xg * 4 + xtig;
    const uint32_t* xsrc = g_xt + (size_t)rows_s[xrow] * DIM + xq * 2;

    const uint32_t* w1p = g_w1t + (size_t)e * 131072;
    const uint32_t* w3p = g_w3t + (size_t)e * 131072;
    const uint32_t* w2p = g_w2t + (size_t)e * 131072;

    // =================== Phase A ===================
    float accA[2][4][2][4] = {};

    // stage chunk c into buf b (phase A)
    auto stageA = [&](int c, int b) {
        uint32_t base = smem_b + (STAGE_BASE + b * STA) * 4;
        const uint32_t* g1 = w1p + c * 4096;
        const uint32_t* g3 = w3p + c * 4096;
        #pragma unroll
        for (int u = 0; u < 2; u++) {
            int un = u * 512 + tid;
            uint32_t d = base + ((un >> 4) * 68 + (un & 15) * 4) * 4;
            CP16(d, g1 + un * 4);
            CP16(d + 4352 * 4, g3 + un * 4);
        }
        CP8(base + (XSUB + xword) * 4, xsrc + c * 16);
    };

    stageA(0, 0); CP_COMMIT();
    stageA(1, 1); CP_COMMIT();
    stageA(2, 2); CP_COMMIT();

    for (int c = 0; c < 32; c++) {
        const int buf = c & 3;
        CP_WAIT2();
        __syncthreads();
        if (c + 3 < 32) stageA(c + 3, (c + 3) & 3);
        CP_COMMIT();

        const int sb0 = STAGE_BASE + buf * STA;
        #pragma unroll
        for (int s = 0; s < 2; s++) {
            uint32_t a[2][4];
            const int ab = sb0 + XSUB + (s * 4 + mg * 2) * 132 + lane;
            #pragma unroll
            for (int r = 0; r < 4; r++) {
                a[0][r] = sm[ab + r * 32];
                a[1][r] = sm[ab + 132 + r * 32];
            }
            #pragma unroll
            for (int mat = 0; mat < 2; mat++) {
                const int wb0 = sb0 + mat * 4352 + (s * 32 + nw * 4) * 68 + perm;
                #pragma unroll
                for (int j = 0; j < 4; j++) {
                    uint32_t b0 = sm[wb0 + j * 68];
                    uint32_t b1 = sm[wb0 + j * 68 + 32];
                    mma8(accA[mat][j][0], a[0], b0, b1);
                    mma8(accA[mat][j][1], a[1], b0, b1);
                }
            }
        }
    }
    CP_WAIT0();
    __syncthreads();

    // ========== SwiGLU -> H fragment planes ==========
    #pragma unroll
    for (int j = 0; j < 4; j++) {
        #pragma unroll
        for (int m = 0; m < 2; m++) {
            #pragma unroll
            for (int r = 0; r < 4; r++) {
                float v1 = accA[0][j][m][r];
                float v3 = accA[1][j][m][r];
                float h  = v1 / (1.0f + __expf(-v1)) * v3;
                int rhalf = r >> 1;
                int hcol  = nw * 32 + j * 8 + tig * 2 + (r & 1);
                int sH    = hcol >> 3;
                int kk2   = hcol & 7;
                int reg2  = rhalf + 2 * (kk2 >> 2);
                sm[HBW + (sH * 4 + mg * 2 + m) * 132 + reg2 * 32 + g * 4 + (kk2 & 3)]
                    = f2tf(h);
            }
        }
    }

    // =================== Phase B ===================
    float accB[8][2][4] = {};

    auto stageB = [&](int c, int b) {
        uint32_t base = smem_b + (STAGE_BASE + b * STB) * 4;
        const uint32_t* g2 = w2p + c * 8192;
        #pragma unroll
        for (int u = 0; u < 4; u++) {
            int un = u * 512 + tid;
            uint32_t d = base + ((un >> 4) * 68 + (un & 15) * 4) * 4;
            CP16(d, g2 + un * 4);
        }
    };

    stageB(0, 0); CP_COMMIT();
    stageB(1, 1); CP_COMMIT();
    stageB(2, 2); CP_COMMIT();

    for (int c = 0; c < 16; c++) {
        const int buf = c & 3;
        CP_WAIT2();
        __syncthreads();
        if (c + 3 < 16) stageB(c + 3, (c + 3) & 3);
        CP_COMMIT();

        const int sb0 = STAGE_BASE + buf * STB;
        #pragma unroll
        for (int s = 0; s < 2; s++) {
            const int sH = c * 2 + s;
            uint32_t a[2][4];
            const int ab = HBW + (sH * 4 + mg * 2) * 132 + lane;
            #pragma unroll
            for (int r = 0; r < 4; r++) {
                a[0][r] = sm[ab + r * 32];
                a[1][r] = sm[ab + 132 + r * 32];
            }
            const int wb0 = sb0 + (s * 64 + nw * 8) * 68 + perm;
            #pragma unroll
            for (int j = 0; j < 8; j++) {
                uint32_t b0 = sm[wb0 + j * 68];
                uint32_t b1 = sm[wb0 + j * 68 + 32];
                mma8(accB[j][0], a[0], b0, b1);
                mma8(accB[j][1], a[1], b0, b1);
            }
        }
    }
    CP_WAIT0();

    // =================== Epilogue ===================
    #pragma unroll
    for (int m = 0; m < 2; m++) {
        #pragma unroll
        for (int rh = 0; rh < 2; rh++) {
            int row = mg * 32 + m * 16 + g + 8 * rh;
            if (row < nr) {
                float wgt = wt_s[row];
                float* op = out + (size_t)rows_s[row] * DIM;
                #pragma unroll
                for (int j = 0; j < 8; j++) {
                    int col = nw * 64 + j * 8 + tig * 2;
                    atomicAdd(op + col,     accB[j][m][rh * 2]     * wgt);
                    atomicAdd(op + col + 1, accB[j][m][rh * 2 + 1] * wgt);
                }
            }
        }
    }
}

// ---------------------------------------------------------------------------
extern "C" void kernel_launch(void* const* d_in, const int* in_sizes, int n_in,
                              void* d_out, int out_size) {
    const float* x      = (const float*)d_in[0];
    const float* gate_w = (const float*)d_in[1];
    const float* gate_b = (const float*)d_in[2];
    const float* w1     = (const float*)d_in[3];
    const float* w3     = (const float*)d_in[4];
    const float* w2     = (const float*)d_in[5];
    float* out = (float*)d_out;

    cudaFuncSetAttribute(ffn_mma_kernel, cudaFuncAttributeMaxDynamicSharedMemorySize, FFN_SMEM);

    prep_kernel<<<(PREP_TOTAL + 255) / 256, 256>>>(
        (const float4*)w1, (const float4*)w3, (const float4*)w2,
        (const float4*)x, (float4*)out);
    gate_kernel<<<T_TOK, 64>>>(x, gate_w, gate_b);
    dim3 grid(CAP / ROWT, NE);
    ffn_mma_kernel<<<grid, THREADS, FFN_SMEM>>>(out);
}

// round 6
// speedup vs baseline: 3.9161x; 1.1498x over previous
#include <cuda_runtime.h>
#include <cuda_fp16.h>
#include <stdint.h>
#include <math.h>

#define T_TOK 2048
#define DIM   512
#define MOE   256
#define NE    64
#define NG    8
#define TOPKG 4
#define KSEL  8
#define RSCALE 2.5f
#define CAP   1024
#define ROWT  64
#define THREADS 512

__device__ int   g_count[NE];
__device__ int   g_rows[NE][CAP];
__device__ float g_wt[NE][CAP];

// fp16 panels (fragment order), packed half2 per word. 65536 words/expert each.
__device__ uint32_t g_w1h[NE * 65536];
__device__ uint32_t g_w3h[NE * 65536];
__device__ uint32_t g_w2h[NE * 65536];
__device__ uint32_t g_xh[T_TOK * 256];

// ---------------------------------------------------------------------------
// smem word map (ffn):  [0,64) rows_s  [64,128) wt_s
//  ring base 128: phase A stride STA=4880 (W1 2176 | W3 2176 | X 528), 8 bufs
//                 phase B stride STB=4352 (W2), 8 bufs (overlaid)
//  HBW = 128 + 8*4880 = 39168 : H frag planes, 64 blocks x 132 = 8448 words
// ---------------------------------------------------------------------------
#define STA 4880
#define STB 4352
#define HBW 39168
#define SMEM_W (39168 + 8448)
#define FFN_SMEM (SMEM_W * 4)

#define CP16(dst_b, src) \
    asm volatile("cp.async.cg.shared.global [%0], [%1], 16;" :: "r"(dst_b), "l"(src))
#define CP4(dst_b, src) \
    asm volatile("cp.async.ca.shared.global [%0], [%1], 4;" :: "r"(dst_b), "l"(src))
#define CP_COMMIT() asm volatile("cp.async.commit_group;" ::: "memory")
#define CP_WAIT6()  asm volatile("cp.async.wait_group 6;" ::: "memory")
#define CP_WAIT0()  asm volatile("cp.async.wait_group 0;" ::: "memory")

__device__ __forceinline__ uint32_t packh2(float lo, float hi) {
    __half2 h = __floats2half2_rn(lo, hi);
    return *(uint32_t*)&h;
}
__device__ __forceinline__ void mma16(float* d, const uint32_t* a,
                                      uint32_t b0, uint32_t b1) {
    asm volatile(
        "mma.sync.aligned.m16n8k16.row.col.f32.f16.f16.f32 "
        "{%0,%1,%2,%3}, {%4,%5,%6,%7}, {%8,%9}, {%0,%1,%2,%3};"
        : "+f"(d[0]), "+f"(d[1]), "+f"(d[2]), "+f"(d[3])
        : "r"(a[0]), "r"(a[1]), "r"(a[2]), "r"(a[3]), "r"(b0), "r"(b1));
}

// ---------------------------------------------------------------------------
// prep: fp32 -> fp16 fragment panels, x -> packed half2, zero out + counters.
// word(k,n) in panel chunk = (n>>3)*64 + (kp>>2)*32 + (n&7)*4 + (kp&3), kp=(k&15)>>1
// half: low = even k.
// ---------------------------------------------------------------------------
#define MQ 1048576
#define XQ 524288
#define OQ 262144
#define PREP_TOTAL (3 * MQ + XQ + OQ)

__global__ void prep_kernel(const float* __restrict__ w1,
                            const float* __restrict__ w3,
                            const float* __restrict__ w2,
                            const float2* __restrict__ x2,
                            float4* __restrict__ out)
{
    unsigned i = blockIdx.x * blockDim.x + threadIdx.x;
    if (i < NE) g_count[i] = 0;
    if (i >= PREP_TOTAL) return;

    if (i < 2 * MQ) {                       // w1 / w3: [E][512 k][256 n]
        const float* src = (i < MQ) ? w1 : w3;
        uint32_t*    dst = (i < MQ) ? g_w1h : g_w3h;
        unsigned j = i & (MQ - 1);
        unsigned e = j >> 14, t = j & 16383;
        unsigned kp = t >> 6, nq = t & 63;
        unsigned k0 = kp * 2, n0 = nq * 4;
        const float4* s4 = (const float4*)(src + (size_t)e * 131072 + k0 * 256 + n0);
        float4 lo = s4[0], hi = s4[64];
        unsigned kpl = (k0 & 15) >> 1;
        unsigned base = e * 65536 + (k0 >> 4) * 2048 + (n0 >> 3) * 64 +
                        (kpl >> 2) * 32 + (kpl & 3) + (n0 & 7) * 4;
        dst[base]      = packh2(lo.x, hi.x);
        dst[base + 4]  = packh2(lo.y, hi.y);
        dst[base + 8]  = packh2(lo.z, hi.z);
        dst[base + 12] = packh2(lo.w, hi.w);
    } else if (i < 3 * MQ) {                // w2: [E][256 k][512 n]
        unsigned j = i - 2 * MQ;
        unsigned e = j >> 14, t = j & 16383;
        unsigned kp = t >> 7, nq = t & 127;
        unsigned k0 = kp * 2, n0 = nq * 4;
        const float4* s4 = (const float4*)(w2 + (size_t)e * 131072 + k0 * 512 + n0);
        float4 lo = s4[0], hi = s4[128];
        unsigned kpl = (k0 & 15) >> 1;
        unsigned base = e * 65536 + (k0 >> 4) * 4096 + (n0 >> 3) * 64 +
                        (kpl >> 2) * 32 + (kpl & 3) + (n0 & 7) * 4;
        g_w2h[base]      = packh2(lo.x, hi.x);
        g_w2h[base + 4]  = packh2(lo.y, hi.y);
        g_w2h[base + 8]  = packh2(lo.z, hi.z);
        g_w2h[base + 12] = packh2(lo.w, hi.w);
    } else if (i < 3 * MQ + XQ) {           // x
        unsigned j = i - 3 * MQ;
        float2 v = x2[j];
        g_xh[j] = packh2(v.x, v.y);
    } else {                                // zero out
        out[i - 3 * MQ - XQ] = make_float4(0.f, 0.f, 0.f, 0.f);
    }
}

// ---------------------------------------------------------------------------
// gating (unchanged, known-good)
// ---------------------------------------------------------------------------
__global__ __launch_bounds__(64) void gate_kernel(
    const float* __restrict__ x,
    const float* __restrict__ gate_w,
    const float* __restrict__ gate_b)
{
    __shared__ float xs[DIM];
    __shared__ float gws[64][68];
    __shared__ float scores[NE];
    __shared__ float sb[NE];

    const int t   = blockIdx.x;
    const int tid = threadIdx.x;

    const float4* x4 = (const float4*)(x + (size_t)t * DIM);
    ((float4*)xs)[tid]      = x4[tid];
    ((float4*)xs)[64 + tid] = x4[64 + tid];
    __syncthreads();

    float acc = 0.0f;
    const float4* gw4 = (const float4*)gate_w;
    for (int kc = 0; kc < DIM; kc += 64) {
        __syncthreads();
        #pragma unroll
        for (int j = 0; j < 16; j++) {
            int idx = j * 64 + tid;
            int e   = idx >> 4;
            int m4  = idx & 15;
            *(float4*)&gws[e][m4 * 4] = gw4[(size_t)e * (DIM/4) + (kc >> 2) + m4];
        }
        __syncthreads();
        #pragma unroll
        for (int kk = 0; kk < 64; kk += 4) {
            float4 wv = *(float4*)&gws[tid][kk];
            float4 xv = *(float4*)&xs[kc + kk];
            acc += xv.x * wv.x + xv.y * wv.y + xv.z * wv.z + xv.w * wv.w;
        }
    }
    float sc = 1.0f / (1.0f + expf(-acc));
    scores[tid] = sc;
    sb[tid]     = sc + gate_b[tid];
    __syncthreads();

    if (tid == 0) {
        const float NEG = -3.0e38f;
        float gsc[NG];
        #pragma unroll
        for (int g = 0; g < NG; g++) {
            float m1 = NEG, m2 = NEG;
            #pragma unroll
            for (int j = 0; j < 8; j++) {
                float v = sb[g * 8 + j];
                if (v > m1) { m2 = m1; m1 = v; }
                else if (v > m2) { m2 = v; }
            }
            gsc[g] = m1 + m2;
        }
        bool gsel[NG];
        #pragma unroll
        for (int g = 0; g < NG; g++) gsel[g] = false;
        for (int it = 0; it < TOPKG; it++) {
            int bg = -1; float bv = NEG;
            #pragma unroll
            for (int g = 0; g < NG; g++)
                if (!gsel[g] && gsc[g] > bv) { bv = gsc[g]; bg = g; }
            gsel[bg] = true;
        }
        for (int e = 0; e < NE; e++)
            if (!gsel[e >> 3]) sb[e] = NEG;
        int   idxs[KSEL];
        float wts[KSEL];
        float wsum = 0.0f;
        for (int k = 0; k < KSEL; k++) {
            int bi = 0; float bv = NEG;
            for (int e = 0; e < NE; e++)
                if (sb[e] > bv) { bv = sb[e]; bi = e; }
            sb[bi] = NEG;
            idxs[k] = bi;
            wts[k]  = scores[bi];
            wsum   += wts[k];
        }
        float inv = RSCALE / wsum;
        for (int k = 0; k < KSEL; k++) {
            int e = idxs[k];
            int pos = atomicAdd(&g_count[e], 1);
            if (pos < CAP) {
                g_rows[e][pos] = t;
                g_wt[e][pos]   = wts[k] * inv;
            }
        }
    }
}

// ---------------------------------------------------------------------------
// FFN: mma.sync fp16 m16n8k16, 8-stage cp.async ring from fp16 panels.
// grid=(CAP/64, NE), 512 threads (16 warps: mg = wid>>3, nw = wid&7).
// ---------------------------------------------------------------------------
__global__ __launch_bounds__(THREADS, 1) void ffn_mma_kernel(
    float* __restrict__ out)
{
    extern __shared__ uint32_t sm[];
    const int e   = blockIdx.y;
    const int cnt = min(g_count[e], CAP);
    const int r0  = blockIdx.x * ROWT;
    if (r0 >= cnt) return;
    const int nr  = min(ROWT, cnt - r0);

    const int tid  = threadIdx.x;
    const int lane = tid & 31, wid = tid >> 5;
    const int g    = lane >> 2, tig = lane & 3;
    const int mg   = wid >> 3, nw = wid & 7;

    int*   rows_s = (int*)sm;
    float* wt_s   = (float*)(sm + 64);
    if (tid < ROWT) {
        rows_s[tid] = (tid < nr) ? g_rows[e][r0 + tid] : 0;
        wt_s[tid]   = (tid < nr) ? g_wt[e][r0 + tid]   : 0.0f;
    }
    __syncthreads();

    uint32_t smem_b;
    asm("{ .reg .u64 t; cvta.to.shared.u64 t, %1; cvt.u32.u64 %0, t; }"
        : "=r"(smem_b) : "l"(sm));

    // per-thread staging constants
    const uint32_t wsts = ((tid >> 4) * 68 + (tid & 15) * 4) * 4;   // CP16 dst (bytes)
    const int xrow = tid >> 3, xkp = tid & 7;
    const int xlr = xrow & 15;
    const uint32_t xw = ((xrow >> 4) * 132 + ((xlr >> 3) + 2 * (xkp >> 2)) * 32 +
                        (xlr & 7) * 4 + (xkp & 3)) * 4;
    const uint32_t* xsrc = g_xh + (size_t)rows_s[xrow] * 256 + xkp;

    const uint32_t* w1p = g_w1h + (size_t)e * 65536;
    const uint32_t* w3p = g_w3h + (size_t)e * 65536;
    const uint32_t* w2p = g_w2h + (size_t)e * 65536;

    // =================== Phase A: 32 k16 chunks ===================
    float accA[2][4][2][4] = {};

    auto stageA = [&](int c, int b) {
        uint32_t base = smem_b + (128 + b * STA) * 4;
        CP16(base + wsts, w1p + c * 2048 + tid * 4);
        CP16(base + 2176 * 4 + wsts, w3p + c * 2048 + tid * 4);
        CP4(base + 4352 * 4 + xw, xsrc + c * 8);
    };

    #pragma unroll
    for (int p = 0; p < 7; p++) { stageA(p, p); CP_COMMIT(); }

    for (int c = 0; c < 32; c++) {
        const int b = c & 7;
        CP_WAIT6();
        __syncthreads();
        if (c + 7 < 32) stageA(c + 7, (c + 7) & 7);
        CP_COMMIT();

        const int sb0 = 128 + b * STA;
        uint32_t a[2][4];
        #pragma unroll
        for (int m = 0; m < 2; m++) {
            const int ab = sb0 + 4352 + (mg * 2 + m) * 132 + lane;
            #pragma unroll
            for (int r = 0; r < 4; r++) a[m][r] = sm[ab + r * 32];
        }
        #pragma unroll
        for (int mat = 0; mat < 2; mat++) {
            #pragma unroll
            for (int j = 0; j < 4; j++) {
                const int off = sb0 + mat * 2176 + (nw * 4 + j) * 68 + lane;
                uint32_t b0 = sm[off], b1 = sm[off + 32];
                mma16(accA[mat][j][0], a[0], b0, b1);
                mma16(accA[mat][j][1], a[1], b0, b1);
            }
        }
    }
    CP_WAIT0();

    // ========== SwiGLU -> H fragment planes (registers -> smem) ==========
    // col = nw*32 + j*8 + tig*2 + (r&1); pack (r, r+1) pairs into half2 words.
    #pragma unroll
    for (int j = 0; j < 4; j++) {
        #pragma unroll
        for (int m = 0; m < 2; m++) {
            float h[4];
            #pragma unroll
            for (int r = 0; r < 4; r++) {
                float v1 = accA[0][j][m][r];
                float v3 = accA[1][j][m][r];
                h[r] = v1 / (1.0f + __expf(-v1)) * v3;
            }
            const int base = HBW + ((nw * 2 + (j >> 1)) * 4 + mg * 2 + m) * 132 +
                             2 * (j & 1) * 32 + lane;
            sm[base]      = packh2(h[0], h[1]);
            sm[base + 32] = packh2(h[2], h[3]);
        }
    }

    // =================== Phase B: 16 k16 chunks over MOE ===================
    float accB[8][2][4] = {};

    auto stageB = [&](int c, int b) {
        uint32_t base = smem_b + (128 + b * STB) * 4;
        CP16(base + wsts, w2p + c * 4096 + tid * 4);
        CP16(base + 32 * 68 * 4 + wsts, w2p + c * 4096 + 2048 + tid * 4);
    };

    #pragma unroll
    for (int p = 0; p < 7; p++) { stageB(p, p); CP_COMMIT(); }

    for (int c = 0; c < 16; c++) {
        const int b = c & 7;
        CP_WAIT6();
        __syncthreads();
        if (c + 7 < 16) stageB(c + 7, (c + 7) & 7);
        CP_COMMIT();

        uint32_t a[2][4];
        #pragma unroll
        for (int m = 0; m < 2; m++) {
            const int ab = HBW + (c * 4 + mg * 2 + m) * 132 + lane;
            #pragma unroll
            for (int r = 0; r < 4; r++) a[m][r] = sm[ab + r * 32];
        }
        const int sb0 = 128 + b * STB;
        #pragma unroll
        for (int j = 0; j < 8; j++) {
            const int off = sb0 + (nw * 8 + j) * 68 + lane;
            uint32_t b0 = sm[off], b1 = sm[off + 32];
            mma16(accB[j][0], a[0], b0, b1);
            mma16(accB[j][1], a[1], b0, b1);
        }
    }
    CP_WAIT0();

    // =================== Epilogue: weighted atomic combine ===================
    #pragma unroll
    for (int m = 0; m < 2; m++) {
        #pragma unroll
        for (int rh = 0; rh < 2; rh++) {
            int row = mg * 32 + m * 16 + g + 8 * rh;
            if (row < nr) {
                float wgt = wt_s[row];
                float* op = out + (size_t)rows_s[row] * DIM;
                #pragma unroll
                for (int j = 0; j < 8; j++) {
                    int col = nw * 64 + j * 8 + tig * 2;
                    atomicAdd(op + col,     accB[j][m][rh * 2]     * wgt);
                    atomicAdd(op + col + 1, accB[j][m][rh * 2 + 1] * wgt);
                }
            }
        }
    }
}

// ---------------------------------------------------------------------------
extern "C" void kernel_launch(void* const* d_in, const int* in_sizes, int n_in,
                              void* d_out, int out_size) {
    const float* x      = (const float*)d_in[0];
    const float* gate_w = (const float*)d_in[1];
    const float* gate_b = (const float*)d_in[2];
    const float* w1     = (const float*)d_in[3];
    const float* w3     = (const float*)d_in[4];
    const float* w2     = (const float*)d_in[5];
    float* out = (float*)d_out;

    cudaFuncSetAttribute(ffn_mma_kernel, cudaFuncAttributeMaxDynamicSharedMemorySize, FFN_SMEM);

    prep_kernel<<<(PREP_TOTAL + 255) / 256, 256>>>(
        w1, w3, w2, (const float2*)x, (float4*)out);
    gate_kernel<<<T_TOK, 64>>>(x, gate_w, gate_b);
    dim3 grid(CAP / ROWT, NE);
    ffn_mma_kernel<<<grid, THREADS, FFN_SMEM>>>(out);
}

// round 7
// speedup vs baseline: 4.0977x; 1.0464x over previous
#include <cuda_runtime.h>
#include <cuda_fp16.h>
#include <stdint.h>
#include <math.h>

#define T_TOK 2048
#define DIM   512
#define MOE   256
#define NE    64
#define NG    8
#define TOPKG 4
#define KSEL  8
#define RSCALE 2.5f
#define CAP   1024
#define ROWT  64
#define THREADS 512
#define NTILES 1024

__device__ int   g_count[NE];
__device__ int   g_rows[NE][CAP];
__device__ float g_wt[NE][CAP];
__device__ int   g_tile;

// fp16 panels (fragment order), packed half2 per word. 65536 words/expert each.
__device__ uint32_t g_w1h[NE * 65536];
__device__ uint32_t g_w3h[NE * 65536];
__device__ uint32_t g_w2h[NE * 65536];
__device__ uint32_t g_xh[T_TOK * 256];

// ---------------------------------------------------------------------------
#define STA 4880
#define STB 4352
#define HBW 39168
#define SMEM_W (39168 + 8448)
#define FFN_SMEM (SMEM_W * 4)

#define CP16(dst_b, src) \
    asm volatile("cp.async.cg.shared.global [%0], [%1], 16;" :: "r"(dst_b), "l"(src))
#define CP4(dst_b, src) \
    asm volatile("cp.async.ca.shared.global [%0], [%1], 4;" :: "r"(dst_b), "l"(src))
#define CP_COMMIT() asm volatile("cp.async.commit_group;" ::: "memory")
#define CP_WAIT6()  asm volatile("cp.async.wait_group 6;" ::: "memory")
#define CP_WAIT0()  asm volatile("cp.async.wait_group 0;" ::: "memory")

__device__ __forceinline__ uint32_t packh2(float lo, float hi) {
    __half2 h = __floats2half2_rn(lo, hi);
    return *(uint32_t*)&h;
}
__device__ __forceinline__ void mma16(float* d, const uint32_t* a,
                                      uint32_t b0, uint32_t b1) {
    asm volatile(
        "mma.sync.aligned.m16n8k16.row.col.f32.f16.f16.f32 "
        "{%0,%1,%2,%3}, {%4,%5,%6,%7}, {%8,%9}, {%0,%1,%2,%3};"
        : "+f"(d[0]), "+f"(d[1]), "+f"(d[2]), "+f"(d[3])
        : "r"(a[0]), "r"(a[1]), "r"(a[2]), "r"(a[3]), "r"(b0), "r"(b1));
}

// ---------------------------------------------------------------------------
// prep v2: smem-staged transpose -> coalesced panel writes.
// grid layout (256 threads/block):
//   [0,2048)    w1 blocks  (e = id>>5, chunk = id&31) : 16k x 256n tile
//   [2048,4096) w3 blocks
//   [4096,5120) w2 blocks  (e = id>>4, chunk = id&15) : 16k x 512n tile
//   [5120,7168) x convert
//   [7168,8192) zero out
// ---------------------------------------------------------------------------
__global__ __launch_bounds__(256) void prep_kernel(
    const float* __restrict__ w1,
    const float* __restrict__ w3,
    const float* __restrict__ w2,
    const float2* __restrict__ x2,
    float4* __restrict__ out)
{
    __shared__ float s[16][516];
    const int b = blockIdx.x;
    const int tid = threadIdx.x;

    if (b == 5120) {
        if (tid < NE) g_count[tid] = 0;
        if (tid == NE) g_tile = 0;
    }

    if (b < 4096) {                       // ---- w1 / w3 ----
        const float* src = (b < 2048) ? w1 : w3;
        uint32_t*    dst = (b < 2048) ? g_w1h : g_w3h;
        const int id = b & 2047;
        const int e = id >> 5, chunk = id & 31;
        const float4* s4 = (const float4*)src + (size_t)e * 32768 + chunk * 16 * 64;
        #pragma unroll
        for (int j = 0; j < 4; j++) {
            int idx = j * 256 + tid;
            int r = idx >> 6, nq = idx & 63;
            *(float4*)&s[r][nq * 4] = s4[r * 64 + nq];
        }
        __syncthreads();
        uint4* d4 = (uint4*)dst + (size_t)e * 16384 + chunk * 512;
        #pragma unroll
        for (int u = 0; u < 2; u++) {
            int W = (tid * 2 + u) * 4;
            int n = (W >> 6) * 8 + ((W >> 2) & 7);
            int rb = ((W >> 5) & 1) * 8;
            uint4 w;
            w.x = packh2(s[rb + 0][n], s[rb + 1][n]);
            w.y = packh2(s[rb + 2][n], s[rb + 3][n]);
            w.z = packh2(s[rb + 4][n], s[rb + 5][n]);
            w.w = packh2(s[rb + 6][n], s[rb + 7][n]);
            d4[tid * 2 + u] = w;
        }
    } else if (b < 5120) {                // ---- w2 ----
        const int id = b - 4096;
        const int e = id >> 4, chunk = id & 15;
        const float4* s4 = (const float4*)w2 + (size_t)e * 32768 + chunk * 16 * 128;
        #pragma unroll
        for (int j = 0; j < 8; j++) {
            int idx = j * 256 + tid;
            int r = idx >> 7, nq = idx & 127;
            *(float4*)&s[r][nq * 4] = s4[r * 128 + nq];
        }
        __syncthreads();
        uint4* d4 = (uint4*)g_w2h + (size_t)e * 16384 + chunk * 1024;
        #pragma unroll
        for (int u = 0; u < 4; u++) {
            int W = (tid * 4 + u) * 4;
            int n = (W >> 6) * 8 + ((W >> 2) & 7);
            int rb = ((W >> 5) & 1) * 8;
            uint4 w;
            w.x = packh2(s[rb + 0][n], s[rb + 1][n]);
            w.y = packh2(s[rb + 2][n], s[rb + 3][n]);
            w.z = packh2(s[rb + 4][n], s[rb + 5][n]);
            w.w = packh2(s[rb + 6][n], s[rb + 7][n]);
            d4[tid * 4 + u] = w;
        }
    } else if (b < 7168) {                // ---- x ----
        int i = (b - 5120) * 256 + tid;
        float2 v = x2[i];
        g_xh[i] = packh2(v.x, v.y);
    } else {                              // ---- zero out ----
        out[(b - 7168) * 256 + tid] = make_float4(0.f, 0.f, 0.f, 0.f);
    }
}

// ---------------------------------------------------------------------------
// gating (unchanged, known-good)
// ---------------------------------------------------------------------------
__global__ __launch_bounds__(64) void gate_kernel(
    const float* __restrict__ x,
    const float* __restrict__ gate_w,
    const float* __restrict__ gate_b)
{
    __shared__ float xs[DIM];
    __shared__ float gws[64][68];
    __shared__ float scores[NE];
    __shared__ float sb[NE];

    const int t   = blockIdx.x;
    const int tid = threadIdx.x;

    const float4* x4 = (const float4*)(x + (size_t)t * DIM);
    ((float4*)xs)[tid]      = x4[tid];
    ((float4*)xs)[64 + tid] = x4[64 + tid];
    __syncthreads();

    float acc = 0.0f;
    const float4* gw4 = (const float4*)gate_w;
    for (int kc = 0; kc < DIM; kc += 64) {
        __syncthreads();
        #pragma unroll
        for (int j = 0; j < 16; j++) {
            int idx = j * 64 + tid;
            int e   = idx >> 4;
            int m4  = idx & 15;
            *(float4*)&gws[e][m4 * 4] = gw4[(size_t)e * (DIM/4) + (kc >> 2) + m4];
        }
        __syncthreads();
        #pragma unroll
        for (int kk = 0; kk < 64; kk += 4) {
            float4 wv = *(float4*)&gws[tid][kk];
            float4 xv = *(float4*)&xs[kc + kk];
            acc += xv.x * wv.x + xv.y * wv.y + xv.z * wv.z + xv.w * wv.w;
        }
    }
    float sc = 1.0f / (1.0f + expf(-acc));
    scores[tid] = sc;
    sb[tid]     = sc + gate_b[tid];
    __syncthreads();

    if (tid == 0) {
        const float NEG = -3.0e38f;
        float gsc[NG];
        #pragma unroll
        for (int g = 0; g < NG; g++) {
            float m1 = NEG, m2 = NEG;
            #pragma unroll
            for (int j = 0; j < 8; j++) {
                float v = sb[g * 8 + j];
                if (v > m1) { m2 = m1; m1 = v; }
                else if (v > m2) { m2 = v; }
            }
            gsc[g] = m1 + m2;
        }
        bool gsel[NG];
        #pragma unroll
        for (int g = 0; g < NG; g++) gsel[g] = false;
        for (int it = 0; it < TOPKG; it++) {
            int bg = -1; float bv = NEG;
            #pragma unroll
            for (int g = 0; g < NG; g++)
                if (!gsel[g] && gsc[g] > bv) { bv = gsc[g]; bg = g; }
            gsel[bg] = true;
        }
        for (int e = 0; e < NE; e++)
            if (!gsel[e >> 3]) sb[e] = NEG;
        int   idxs[KSEL];
        float wts[KSEL];
        float wsum = 0.0f;
        for (int k = 0; k < KSEL; k++) {
            int bi = 0; float bv = NEG;
            for (int e = 0; e < NE; e++)
                if (sb[e] > bv) { bv = sb[e]; bi = e; }
            sb[bi] = NEG;
            idxs[k] = bi;
            wts[k]  = scores[bi];
            wsum   += wts[k];
        }
        float inv = RSCALE / wsum;
        for (int k = 0; k < KSEL; k++) {
            int e = idxs[k];
            int pos = atomicAdd(&g_count[e], 1);
            if (pos < CAP) {
                g_rows[e][pos] = t;
                g_wt[e][pos]   = wts[k] * inv;
            }
        }
    }
}

// ---------------------------------------------------------------------------
// FFN: persistent blocks popping tiles; mma.sync fp16 m16n8k16; 8-stage ring.
// tile id t: e = t&63, r0 = (t>>6)*64 (slot-major order balances load)
// ---------------------------------------------------------------------------
__global__ __launch_bounds__(THREADS, 1) void ffn_mma_kernel(
    float* __restrict__ out)
{
    extern __shared__ uint32_t sm[];
    __shared__ int cur_t;

    const int tid  = threadIdx.x;
    const int lane = tid & 31, wid = tid >> 5;
    const int g    = lane >> 2, tig = lane & 3;
    const int mg   = wid >> 3, nw = wid & 7;

    uint32_t smem_b;
    asm("{ .reg .u64 t; cvta.to.shared.u64 t, %1; cvt.u32.u64 %0, t; }"
        : "=r"(smem_b) : "l"(sm));

    const uint32_t wsts = ((tid >> 4) * 68 + (tid & 15) * 4) * 4;
    const int xrow = tid >> 3, xkp = tid & 7;
    const int xlr = xrow & 15;
    const uint32_t xw = ((xrow >> 4) * 132 + ((xlr >> 3) + 2 * (xkp >> 2)) * 32 +
                        (xlr & 7) * 4 + (xkp & 3)) * 4;

    int*   rows_s = (int*)sm;
    float* wt_s   = (float*)(sm + 64);

    for (;;) {
        __syncthreads();                       // protect cur_t + smem reuse
        if (tid == 0) cur_t = atomicAdd(&g_tile, 1);
        __syncthreads();
        const int t = cur_t;
        if (t >= NTILES) break;

        const int e   = t & 63;
        const int r0  = (t >> 6) * 64;
        const int cnt = min(g_count[e], CAP);
        if (r0 >= cnt) continue;
        const int nr = min(ROWT, cnt - r0);

        if (tid < ROWT) {
            rows_s[tid] = (tid < nr) ? g_rows[e][r0 + tid] : 0;
            wt_s[tid]   = (tid < nr) ? g_wt[e][r0 + tid]   : 0.0f;
        }
        __syncthreads();

        const uint32_t* xsrc = g_xh + (size_t)rows_s[xrow] * 256 + xkp;
        const uint32_t* w1p = g_w1h + (size_t)e * 65536;
        const uint32_t* w3p = g_w3h + (size_t)e * 65536;
        const uint32_t* w2p = g_w2h + (size_t)e * 65536;

        // =================== Phase A: 32 k16 chunks ===================
        float accA[2][4][2][4] = {};

        auto stageA = [&](int c, int b) {
            uint32_t base = smem_b + (128 + b * STA) * 4;
            CP16(base + wsts, w1p + c * 2048 + tid * 4);
            CP16(base + 2176 * 4 + wsts, w3p + c * 2048 + tid * 4);
            CP4(base + 4352 * 4 + xw, xsrc + c * 8);
        };

        #pragma unroll
        for (int p = 0; p < 7; p++) { stageA(p, p); CP_COMMIT(); }

        for (int c = 0; c < 32; c++) {
            const int b = c & 7;
            CP_WAIT6();
            __syncthreads();
            if (c + 7 < 32) stageA(c + 7, (c + 7) & 7);
            CP_COMMIT();

            const int sb0 = 128 + b * STA;
            uint32_t a[2][4];
            #pragma unroll
            for (int m = 0; m < 2; m++) {
                const int ab = sb0 + 4352 + (mg * 2 + m) * 132 + lane;
                #pragma unroll
                for (int r = 0; r < 4; r++) a[m][r] = sm[ab + r * 32];
            }
            #pragma unroll
            for (int mat = 0; mat < 2; mat++) {
                #pragma unroll
                for (int j = 0; j < 4; j++) {
                    const int off = sb0 + mat * 2176 + (nw * 4 + j) * 68 + lane;
                    uint32_t b0 = sm[off], b1 = sm[off + 32];
                    mma16(accA[mat][j][0], a[0], b0, b1);
                    mma16(accA[mat][j][1], a[1], b0, b1);
                }
            }
        }
        CP_WAIT0();

        // ========== SwiGLU -> H fragment planes ==========
        #pragma unroll
        for (int j = 0; j < 4; j++) {
            #pragma unroll
            for (int m = 0; m < 2; m++) {
                float h[4];
                #pragma unroll
                for (int r = 0; r < 4; r++) {
                    float v1 = accA[0][j][m][r];
                    float v3 = accA[1][j][m][r];
                    h[r] = v1 / (1.0f + __expf(-v1)) * v3;
                }
                const int base = HBW + ((nw * 2 + (j >> 1)) * 4 + mg * 2 + m) * 132 +
                                 2 * (j & 1) * 32 + lane;
                sm[base]      = packh2(h[0], h[1]);
                sm[base + 32] = packh2(h[2], h[3]);
            }
        }

        // =================== Phase B: 16 k16 chunks ===================
        float accB[8][2][4] = {};

        auto stageB = [&](int c, int b) {
            uint32_t base = smem_b + (128 + b * STB) * 4;
            CP16(base + wsts, w2p + c * 4096 + tid * 4);
            CP16(base + 32 * 68 * 4 + wsts, w2p + c * 4096 + 2048 + tid * 4);
        };

        #pragma unroll
        for (int p = 0; p < 7; p++) { stageB(p, p); CP_COMMIT(); }

        for (int c = 0; c < 16; c++) {
            const int b = c & 7;
            CP_WAIT6();
            __syncthreads();
            if (c + 7 < 16) stageB(c + 7, (c + 7) & 7);
            CP_COMMIT();

            uint32_t a[2][4];
            #pragma unroll
            for (int m = 0; m < 2; m++) {
                const int ab = HBW + (c * 4 + mg * 2 + m) * 132 + lane;
                #pragma unroll
                for (int r = 0; r < 4; r++) a[m][r] = sm[ab + r * 32];
            }
            const int sb0 = 128 + b * STB;
            #pragma unroll
            for (int j = 0; j < 8; j++) {
                const int off = sb0 + (nw * 8 + j) * 68 + lane;
                uint32_t b0 = sm[off], b1 = sm[off + 32];
                mma16(accB[j][0], a[0], b0, b1);
                mma16(accB[j][1], a[1], b0, b1);
            }
        }
        CP_WAIT0();

        // =================== Epilogue ===================
        #pragma unroll
        for (int m = 0; m < 2; m++) {
            #pragma unroll
            for (int rh = 0; rh < 2; rh++) {
                int row = mg * 32 + m * 16 + g + 8 * rh;
                if (row < nr) {
                    float wgt = wt_s[row];
                    float* op = out + (size_t)rows_s[row] * DIM;
                    #pragma unroll
                    for (int j = 0; j < 8; j++) {
                        int col = nw * 64 + j * 8 + tig * 2;
                        atomicAdd(op + col,     accB[j][m][rh * 2]     * wgt);
                        atomicAdd(op + col + 1, accB[j][m][rh * 2 + 1] * wgt);
                    }
                }
            }
        }
    }
}

// ---------------------------------------------------------------------------
extern "C" void kernel_launch(void* const* d_in, const int* in_sizes, int n_in,
                              void* d_out, int out_size) {
    const float* x      = (const float*)d_in[0];
    const float* gate_w = (const float*)d_in[1];
    const float* gate_b = (const float*)d_in[2];
    const float* w1     = (const float*)d_in[3];
    const float* w3     = (const float*)d_in[4];
    const float* w2     = (const float*)d_in[5];
    float* out = (float*)d_out;

    cudaFuncSetAttribute(ffn_mma_kernel, cudaFuncAttributeMaxDynamicSharedMemorySize, FFN_SMEM);

    prep_kernel<<<8192, 256>>>(w1, w3, w2, (const float2*)x, (float4*)out);
    gate_kernel<<<T_TOK, 64>>>(x, gate_w, gate_b);
    ffn_mma_kernel<<<152, THREADS, FFN_SMEM>>>(out);
}

// round 8
// speedup vs baseline: 4.5864x; 1.1193x over previous
#include <cuda_runtime.h>
#include <cuda_fp16.h>
#include <stdint.h>
#include <math.h>

#define T_TOK 2048
#define DIM   512
#define MOE   256
#define NE    64
#define NG    8
#define TOPKG 4
#define KSEL  8
#define RSCALE 2.5f
#define CAP   1024
#define ROWT  64
#define THREADS 512
#define NTILES 1024

__device__ int   g_count[NE];
__device__ int   g_rows[NE][CAP];
__device__ float g_wt[NE][CAP];
__device__ int   g_tile;

// fp16 panels (vector-fragment order), packed half2 words. 65536 words/expert.
__device__ uint32_t g_w1h[NE * 65536];
__device__ uint32_t g_w3h[NE * 65536];
__device__ uint32_t g_w2h[NE * 65536];
__device__ uint32_t g_xh[T_TOK * 256];

// ---------------------------------------------------------------------------
// ffn smem word map:
//  [0,64) rows_s  [64,128) wt_s
//  ring base 128: phase A stride STA=4608 (W1 2048 | W3 2048 | X 512), 8 bufs
//                 phase B stride STB=4096 (W2), 8 bufs (overlaid)
//  HBW = 128 + 8*4608 = 36992 : H planes 16c x 4mf x 128 = 8192 words
// ---------------------------------------------------------------------------
#define STA 4608
#define STB 4096
#define HBW 36992
#define SMEM_W (36992 + 8192)
#define FFN_SMEM (SMEM_W * 4)

#define CP16(dst_b, src) \
    asm volatile("cp.async.cg.shared.global [%0], [%1], 16;" :: "r"(dst_b), "l"(src))
#define CP4(dst_b, src) \
    asm volatile("cp.async.ca.shared.global [%0], [%1], 4;" :: "r"(dst_b), "l"(src))
#define CP_COMMIT() asm volatile("cp.async.commit_group;" ::: "memory")
#define CP_WAIT6()  asm volatile("cp.async.wait_group 6;" ::: "memory")
#define CP_WAIT0()  asm volatile("cp.async.wait_group 0;" ::: "memory")

__device__ __forceinline__ uint32_t packh2(float lo, float hi) {
    __half2 h = __floats2half2_rn(lo, hi);
    return *(uint32_t*)&h;
}
__device__ __forceinline__ void mma16(float* d, uint32_t a0, uint32_t a1,
                                      uint32_t a2, uint32_t a3,
                                      uint32_t b0, uint32_t b1) {
    asm volatile(
        "mma.sync.aligned.m16n8k16.row.col.f32.f16.f16.f32 "
        "{%0,%1,%2,%3}, {%4,%5,%6,%7}, {%8,%9}, {%0,%1,%2,%3};"
        : "+f"(d[0]), "+f"(d[1]), "+f"(d[2]), "+f"(d[3])
        : "r"(a0), "r"(a1), "r"(a2), "r"(a3), "r"(b0), "r"(b1));
}

// ---------------------------------------------------------------------------
__global__ void zero_small() {
    if (threadIdx.x < NE) g_count[threadIdx.x] = 0;
    if (threadIdx.x == NE) g_tile = 0;
}

// ---------------------------------------------------------------------------
// prep+gate merged.  256 threads/block.  dyn smem 8256 floats.
// blocks: [0,2048) w1 | [2048,4096) w3 | [4096,5120) w2 |
//         [5120,7168) x | [7168,8192) zero out | [8192,8704) gate (4 tok/blk)
// Panel word order per k16 chunk:
//   W (w1/w3, 2048 words): jg=W>>6, li=(W&63)>>1, regi=W&1; n=jg*8+(li>>2);
//   kp=(li&3)+4*regi; value=half2(w[2kp][n], w[2kp+1][n])
//   (w2 identical, 4096 words, jg=W>>6 in [0,64))
// ---------------------------------------------------------------------------
__global__ __launch_bounds__(256) void prep_gate_kernel(
    const float* __restrict__ w1,
    const float* __restrict__ w3,
    const float* __restrict__ w2,
    const float2* __restrict__ x2,
    const float* __restrict__ gate_w,
    const float* __restrict__ gate_b,
    float4* __restrict__ out)
{
    extern __shared__ float ps[];
    const int b = blockIdx.x;
    const int tid = threadIdx.x;

    if (b < 4096) {                       // ---- w1 / w3 ----
        float (*s)[516] = (float(*)[516])ps;
        const float* src = (b < 2048) ? w1 : w3;
        uint32_t*    dst = (b < 2048) ? g_w1h : g_w3h;
        const int id = b & 2047;
        const int e = id >> 5, chunk = id & 31;
        const float4* s4 = (const float4*)src + (size_t)e * 32768 + chunk * 16 * 64;
        #pragma unroll
        for (int j = 0; j < 4; j++) {
            int idx = j * 256 + tid;
            int r = idx >> 6, nq = idx & 63;
            *(float4*)&s[r][nq * 4] = s4[r * 64 + nq];
        }
        __syncthreads();
        uint4* d4 = (uint4*)dst + (size_t)e * 16384 + chunk * 512;
        #pragma unroll
        for (int u = 0; u < 2; u++) {
            uint32_t v[4];
            #pragma unroll
            for (int q = 0; q < 4; q++) {
                int W = (tid * 2 + u) * 4 + q;
                int jg = W >> 6, li = (W & 63) >> 1, regi = W & 1;
                int n = jg * 8 + (li >> 2);
                int klo = 2 * ((li & 3) + 4 * regi);
                v[q] = packh2(s[klo][n], s[klo + 1][n]);
            }
            d4[tid * 2 + u] = make_uint4(v[0], v[1], v[2], v[3]);
        }
    } else if (b < 5120) {                // ---- w2 ----
        float (*s)[516] = (float(*)[516])ps;
        const int id = b - 4096;
        const int e = id >> 4, chunk = id & 15;
        const float4* s4 = (const float4*)w2 + (size_t)e * 32768 + chunk * 16 * 128;
        #pragma unroll
        for (int j = 0; j < 8; j++) {
            int idx = j * 256 + tid;
            int r = idx >> 7, nq = idx & 127;
            *(float4*)&s[r][nq * 4] = s4[r * 128 + nq];
        }
        __syncthreads();
        uint4* d4 = (uint4*)g_w2h + (size_t)e * 16384 + chunk * 1024;
        #pragma unroll
        for (int u = 0; u < 4; u++) {
            uint32_t v[4];
            #pragma unroll
            for (int q = 0; q < 4; q++) {
                int W = (tid * 4 + u) * 4 + q;
                int jg = W >> 6, li = (W & 63) >> 1, regi = W & 1;
                int n = jg * 8 + (li >> 2);
                int klo = 2 * ((li & 3) + 4 * regi);
                v[q] = packh2(s[klo][n], s[klo + 1][n]);
            }
            d4[tid * 4 + u] = make_uint4(v[0], v[1], v[2], v[3]);
        }
    } else if (b < 7168) {                // ---- x ----
        int i = (b - 5120) * 256 + tid;
        float2 v = x2[i];
        g_xh[i] = packh2(v.x, v.y);
    } else if (b < 8192) {                // ---- zero out ----
        out[(b - 7168) * 256 + tid] = make_float4(0.f, 0.f, 0.f, 0.f);
    } else {                              // ---- gate: 4 tokens/block ----
        float* xs     = ps;               // [4][512]
        float (*gws)[68] = (float(*)[68])(ps + 2048);   // [64][68]
        float* scores = ps + 6400;        // [4][64]
        float* sb     = ps + 6656;        // [4][64]

        const int t0  = (b - 8192) * 4;
        const int tg  = tid >> 6, te = tid & 63;
        const float* x = (const float*)x2;

        const float4* xr = (const float4*)(x + (size_t)(t0 + tg) * DIM);
        ((float4*)(xs + tg * DIM))[te]      = xr[te];
        ((float4*)(xs + tg * DIM))[64 + te] = xr[64 + te];
        __syncthreads();

        float acc = 0.0f;
        const float4* gw4 = (const float4*)gate_w;
        for (int kc = 0; kc < DIM; kc += 64) {
            __syncthreads();
            #pragma unroll
            for (int j = 0; j < 4; j++) {
                int idx = j * 256 + tid;
                int e   = idx >> 4;
                int m4  = idx & 15;
                *(float4*)&gws[e][m4 * 4] = gw4[(size_t)e * (DIM/4) + (kc >> 2) + m4];
            }
            __syncthreads();
            #pragma unroll
            for (int kk = 0; kk < 64; kk += 4) {
                float4 wv = *(float4*)&gws[te][kk];
                float4 xv = *(float4*)&xs[tg * DIM + kc + kk];
                acc += xv.x * wv.x + xv.y * wv.y + xv.z * wv.z + xv.w * wv.w;
            }
        }
        float sc = 1.0f / (1.0f + expf(-acc));
        scores[tg * 64 + te] = sc;
        sb[tg * 64 + te]     = sc + gate_b[te];
        __syncthreads();

        if (te == 0) {
            float* sbT = sb + tg * 64;
            float* scT = scores + tg * 64;
            const int t = t0 + tg;
            const float NEG = -3.0e38f;
            float gsc[NG];
            #pragma unroll
            for (int g = 0; g < NG; g++) {
                float m1 = NEG, m2 = NEG;
                #pragma unroll
                for (int j = 0; j < 8; j++) {
                    float v = sbT[g * 8 + j];
                    if (v > m1) { m2 = m1; m1 = v; }
                    else if (v > m2) { m2 = v; }
                }
                gsc[g] = m1 + m2;
            }
            bool gsel[NG];
            #pragma unroll
            for (int g = 0; g < NG; g++) gsel[g] = false;
            for (int it = 0; it < TOPKG; it++) {
                int bg = -1; float bv = NEG;
                #pragma unroll
                for (int g = 0; g < NG; g++)
                    if (!gsel[g] && gsc[g] > bv) { bv = gsc[g]; bg = g; }
                gsel[bg] = true;
            }
            for (int e = 0; e < NE; e++)
                if (!gsel[e >> 3]) sbT[e] = NEG;
            int   idxs[KSEL];
            float wts[KSEL];
            float wsum = 0.0f;
            for (int k = 0; k < KSEL; k++) {
                int bi = 0; float bv = NEG;
                for (int e = 0; e < NE; e++)
                    if (sbT[e] > bv) { bv = sbT[e]; bi = e; }
                sbT[bi] = NEG;
                idxs[k] = bi;
                wts[k]  = scT[bi];
                wsum   += wts[k];
            }
            float inv = RSCALE / wsum;
            for (int k = 0; k < KSEL; k++) {
                int e = idxs[k];
                int pos = atomicAdd(&g_count[e], 1);
                if (pos < CAP) {
                    g_rows[e][pos] = t;
                    g_wt[e][pos]   = wts[k] * inv;
                }
            }
        }
    }
}

// ---------------------------------------------------------------------------
// FFN: persistent, mma.sync fp16 m16n8k16, vectorized fragment planes.
// A-frag = 1 LDS.128 (word = lane*4+reg), B-frag = 1 LDS.64 (word = lane*2+reg)
// ---------------------------------------------------------------------------
__global__ __launch_bounds__(THREADS, 1) void ffn_mma_kernel(
    float* __restrict__ out)
{
    extern __shared__ uint32_t sm[];
    __shared__ int cur_t;

    const int tid  = threadIdx.x;
    const int lane = tid & 31, wid = tid >> 5;
    const int g    = lane >> 2, tig = lane & 3;
    const int mg   = wid >> 3, nw = wid & 7;

    uint32_t smem_b;
    asm("{ .reg .u64 t; cvta.to.shared.u64 t, %1; cvt.u32.u64 %0, t; }"
        : "=r"(smem_b) : "l"(sm));

    // X staging slot (bytes within X region)
    const int xrow = tid >> 3, xkp = tid & 7;
    const uint32_t xw = ((xrow >> 4) * 128 + ((xrow & 7) * 4 + (xkp & 3)) * 4 +
                        ((xrow >> 3) & 1) + 2 * (xkp >> 2)) * 4;

    int*   rows_s = (int*)sm;
    float* wt_s   = (float*)(sm + 64);

    for (;;) {
        __syncthreads();
        if (tid == 0) cur_t = atomicAdd(&g_tile, 1);
        __syncthreads();
        const int t = cur_t;
        if (t >= NTILES) break;

        const int e   = t & 63;
        const int r0  = (t >> 6) * 64;
        const int cnt = min(g_count[e], CAP);
        if (r0 >= cnt) continue;
        const int nr = min(ROWT, cnt - r0);

        if (tid < ROWT) {
            rows_s[tid] = (tid < nr) ? g_rows[e][r0 + tid] : 0;
            wt_s[tid]   = (tid < nr) ? g_wt[e][r0 + tid]   : 0.0f;
        }
        __syncthreads();

        const uint32_t* xsrc = g_xh + (size_t)rows_s[xrow] * 256 + xkp;
        const uint32_t* w1p = g_w1h + (size_t)e * 65536;
        const uint32_t* w3p = g_w3h + (size_t)e * 65536;
        const uint32_t* w2p = g_w2h + (size_t)e * 65536;

        // =================== Phase A: 32 k16 chunks ===================
        float accA[2][4][2][4] = {};

        auto stageA = [&](int c, int b) {
            uint32_t base = smem_b + (128 + b * STA) * 4;
            CP16(base + tid * 16, w1p + c * 2048 + tid * 4);
            CP16(base + 8192 + tid * 16, w3p + c * 2048 + tid * 4);
            CP4(base + 16384 + xw, xsrc + c * 8);
        };

        #pragma unroll
        for (int p = 0; p < 7; p++) { stageA(p, p); CP_COMMIT(); }

        for (int c = 0; c < 32; c++) {
            const int b = c & 7;
            CP_WAIT6();
            __syncthreads();
            if (c + 7 < 32) stageA(c + 7, (c + 7) & 7);
            CP_COMMIT();

            const int sb0 = 128 + b * STA;
            uint4 a[2];
            #pragma unroll
            for (int m = 0; m < 2; m++)
                a[m] = *(const uint4*)&sm[sb0 + 4096 + (mg * 2 + m) * 128 + lane * 4];
            #pragma unroll
            for (int mat = 0; mat < 2; mat++) {
                #pragma unroll
                for (int j = 0; j < 4; j++) {
                    uint2 bv = *(const uint2*)&sm[sb0 + mat * 2048 +
                                                  (nw * 4 + j) * 64 + lane * 2];
                    mma16(accA[mat][j][0], a[0].x, a[0].y, a[0].z, a[0].w, bv.x, bv.y);
                    mma16(accA[mat][j][1], a[1].x, a[1].y, a[1].z, a[1].w, bv.x, bv.y);
                }
            }
        }
        CP_WAIT0();

        // ========== SwiGLU -> H planes (STS.64 each) ==========
        #pragma unroll
        for (int j = 0; j < 4; j++) {
            #pragma unroll
            for (int m = 0; m < 2; m++) {
                float h[4];
                #pragma unroll
                for (int r = 0; r < 4; r++) {
                    float v1 = accA[0][j][m][r];
                    float v3 = accA[1][j][m][r];
                    h[r] = v1 / (1.0f + __expf(-v1)) * v3;
                }
                const int base = HBW + ((nw * 2 + (j >> 1)) * 4 + mg * 2 + m) * 128 +
                                 lane * 4 + 2 * (j & 1);
                *(uint2*)&sm[base] = make_uint2(packh2(h[0], h[1]), packh2(h[2], h[3]));
            }
        }

        // =================== Phase B: 16 k16 chunks ===================
        float accB[8][2][4] = {};

        auto stageB = [&](int c, int b) {
            uint32_t base = smem_b + (128 + b * STB) * 4;
            CP16(base + tid * 16, w2p + c * 4096 + tid * 4);
            CP16(base + 8192 + tid * 16, w2p + c * 4096 + 2048 + tid * 4);
        };

        #pragma unroll
        for (int p = 0; p < 7; p++) { stageB(p, p); CP_COMMIT(); }

        for (int c = 0; c < 16; c++) {
            const int b = c & 7;
            CP_WAIT6();
            __syncthreads();
            if (c + 7 < 16) stageB(c + 7, (c + 7) & 7);
            CP_COMMIT();

            uint4 a[2];
            #pragma unroll
            for (int m = 0; m < 2; m++)
                a[m] = *(const uint4*)&sm[HBW + (c * 4 + mg * 2 + m) * 128 + lane * 4];
            const int sb0 = 128 + b * STB;
            #pragma unroll
            for (int j = 0; j < 8; j++) {
                uint2 bv = *(const uint2*)&sm[sb0 + (nw * 8 + j) * 64 + lane * 2];
                mma16(accB[j][0], a[0].x, a[0].y, a[0].z, a[0].w, bv.x, bv.y);
                mma16(accB[j][1], a[1].x, a[1].y, a[1].z, a[1].w, bv.x, bv.y);
            }
        }
        CP_WAIT0();

        // =================== Epilogue ===================
        #pragma unroll
        for (int m = 0; m < 2; m++) {
            #pragma unroll
            for (int rh = 0; rh < 2; rh++) {
                int row = mg * 32 + m * 16 + g + 8 * rh;
                if (row < nr) {
                    float wgt = wt_s[row];
                    float* op = out + (size_t)rows_s[row] * DIM;
                    #pragma unroll
                    for (int j = 0; j < 8; j++) {
                        int col = nw * 64 + j * 8 + tig * 2;
                        atomicAdd(op + col,     accB[j][m][rh * 2]     * wgt);
                        atomicAdd(op + col + 1, accB[j][m][rh * 2 + 1] * wgt);
                    }
                }
            }
        }
    }
}

// ---------------------------------------------------------------------------
extern "C" void kernel_launch(void* const* d_in, const int* in_sizes, int n_in,
                              void* d_out, int out_size) {
    const float* x      = (const float*)d_in[0];
    const float* gate_w = (const float*)d_in[1];
    const float* gate_b = (const float*)d_in[2];
    const float* w1     = (const float*)d_in[3];
    const float* w3     = (const float*)d_in[4];
    const float* w2     = (const float*)d_in[5];
    float* out = (float*)d_out;

    cudaFuncSetAttribute(ffn_mma_kernel, cudaFuncAttributeMaxDynamicSharedMemorySize, FFN_SMEM);

    zero_small<<<1, 128>>>();
    prep_gate_kernel<<<8704, 256, 8256 * 4>>>(
        w1, w3, w2, (const float2*)x, gate_w, gate_b, (float4*)out);
    ffn_mma_kernel<<<152, THREADS, FFN_SMEM>>>(out);
}